// round 1
// baseline (speedup 1.0000x reference)
#include <cuda_runtime.h>
#include <cuda_bf16.h>
#include <math.h>

// ---------------- problem constants ----------------
#define BATCH 4
#define NROI 1632
#define DIN 1632
#define DMODEL 256
#define NHEAD 4
#define DHEAD 64
#define DFF 1024
#define SEQ 3375          // 15^3
#define ROWS_X (BATCH*SEQ)   // 13500
#define ROWS_Q (BATCH*NROI)  // 6528
#define LN_EPS 1e-5f

// ---------------- scratch (device globals; no allocation allowed) ----------------
__device__ float g_Q[ROWS_Q * DMODEL];          // ROI embeddings
__device__ float g_x[ROWS_X * DMODEL];          // tokens / running x
__device__ float g_x2[ROWS_X * DMODEL];
__device__ float g_qkv[ROWS_X * 3 * DMODEL];
__device__ float g_q[BATCH * NHEAD * SEQ * DHEAD];
__device__ float g_k[BATCH * NHEAD * SEQ * DHEAD];
__device__ float g_v[BATCH * NHEAD * SEQ * DHEAD];
__device__ float g_o[ROWS_X * DMODEL];          // merged attention output
__device__ float g_t[ROWS_X * DMODEL];          // temp (proj out / ffn2 out)
__device__ float g_h[ROWS_X * DFF];             // ffn hidden
__device__ float g_y[ROWS_X * DMODEL];          // final LN output
__device__ float g_part[BATCH * 8 * DMODEL];    // partial sums for mean

// ---------------- helpers ----------------
__device__ __forceinline__ float gelu_exact(float x) {
    return 0.5f * x * (1.0f + erff(x * 0.70710678118654752f));
}

// ---------------- SGEMM: C[m,n] = act(sum_k A[m,k]*B[n,k] + bias[n]) ----------------
// BM=BN=128, BK=8, 256 threads, 8x8 microtile. Requires K % 8 == 0.
#define BM 128
#define BN 128
#define BK 8

__global__ void __launch_bounds__(256, 2)
sgemm_nt(const float* __restrict__ A, const float* __restrict__ B,
         const float* __restrict__ bias, float* __restrict__ C,
         int M, int N, int K, int act) {
    __shared__ float As[BK][BM];
    __shared__ float Bs[BK][BN];
    const int bm = blockIdx.y * BM;
    const int bn = blockIdx.x * BN;
    const int tid = threadIdx.x;
    const int ty = tid >> 4;        // 0..15
    const int tx = tid & 15;        // 0..15
    const int lrow = tid >> 1;      // 0..127
    const int lcol = (tid & 1) << 2; // 0 or 4

    float acc[8][8];
#pragma unroll
    for (int i = 0; i < 8; i++)
#pragma unroll
        for (int j = 0; j < 8; j++) acc[i][j] = 0.f;

    for (int k0 = 0; k0 < K; k0 += BK) {
        float4 a4 = make_float4(0.f, 0.f, 0.f, 0.f);
        int ar = bm + lrow;
        if (ar < M) a4 = *reinterpret_cast<const float4*>(&A[(size_t)ar * K + k0 + lcol]);
        As[lcol + 0][lrow] = a4.x;
        As[lcol + 1][lrow] = a4.y;
        As[lcol + 2][lrow] = a4.z;
        As[lcol + 3][lrow] = a4.w;

        float4 b4 = make_float4(0.f, 0.f, 0.f, 0.f);
        int br = bn + lrow;
        if (br < N) b4 = *reinterpret_cast<const float4*>(&B[(size_t)br * K + k0 + lcol]);
        Bs[lcol + 0][lrow] = b4.x;
        Bs[lcol + 1][lrow] = b4.y;
        Bs[lcol + 2][lrow] = b4.z;
        Bs[lcol + 3][lrow] = b4.w;
        __syncthreads();

#pragma unroll
        for (int k = 0; k < BK; k++) {
            float ar_[8], br_[8];
#pragma unroll
            for (int i = 0; i < 8; i++) ar_[i] = As[k][ty * 8 + i];
#pragma unroll
            for (int j = 0; j < 8; j++) br_[j] = Bs[k][tx * 8 + j];
#pragma unroll
            for (int i = 0; i < 8; i++)
#pragma unroll
                for (int j = 0; j < 8; j++) acc[i][j] += ar_[i] * br_[j];
        }
        __syncthreads();
    }

#pragma unroll
    for (int i = 0; i < 8; i++) {
        int row = bm + ty * 8 + i;
        if (row >= M) continue;
#pragma unroll
        for (int j = 0; j < 8; j++) {
            int col = bn + tx * 8 + j;
            if (col >= N) continue;
            float vv = acc[i][j] + bias[col];
            if (act == 1) vv = gelu_exact(vv);
            C[(size_t)row * N + col] = vv;
        }
    }
}

// ---------------- FNN is sgemm + gelu (act=1) on F ----------------

// ---------------- gather + sum-pool ----------------
// out[b, o, d] = sum_{dx,dy,dz in 0..2} Q[b, C[b, 2ox+dx, 2oy+dy, 2oz+dz], d]
__global__ void gather_pool(const float* __restrict__ Q, const int* __restrict__ C,
                            float* __restrict__ out) {
    int o = blockIdx.x;     // 0..3374
    int b = blockIdx.y;
    int d = threadIdx.x;    // 0..255
    int oz = o % 15;
    int oy = (o / 15) % 15;
    int ox = o / 225;
    const float* Qb = Q + (size_t)b * NROI * DMODEL;
    const int* Cb = C + (size_t)b * 32 * 32 * 32;
    float acc = 0.f;
#pragma unroll
    for (int dx = 0; dx < 3; dx++) {
        int x = 2 * ox + dx;
#pragma unroll
        for (int dy = 0; dy < 3; dy++) {
            int y = 2 * oy + dy;
#pragma unroll
            for (int dz = 0; dz < 3; dz++) {
                int z = 2 * oz + dz;
                int idx = Cb[(x * 32 + y) * 32 + z];
                acc += Qb[(size_t)idx * DMODEL + d];
            }
        }
    }
    out[((size_t)b * SEQ + o) * DMODEL + d] = acc;
}

// ---------------- split qkv into (B,H,S,DH), scale q by 1/8 ----------------
__global__ void split_qkv(const float* __restrict__ qkv, float* __restrict__ q,
                          float* __restrict__ k, float* __restrict__ v) {
    int t = blockIdx.x * blockDim.x + threadIdx.x;
    if (t >= ROWS_X * DMODEL) return;
    int d = t & 255;
    int s = (t >> 8) % SEQ;
    int b = t / (256 * SEQ);
    int h = d >> 6;
    int dh = d & 63;
    size_t src = (size_t)(b * SEQ + s) * (3 * DMODEL);
    size_t dst = ((size_t)(b * NHEAD + h) * SEQ + s) * DHEAD + dh;
    q[dst] = qkv[src + d] * 0.125f;
    k[dst] = qkv[src + DMODEL + d];
    v[dst] = qkv[src + 2 * DMODEL + d];
}

// ---------------- flash attention (fp32, online softmax) ----------------
// grid: (ceil(S/64), B*H), 256 threads. Writes merged (B,S,D) output.
__global__ void __launch_bounds__(256, 2)
flash_attn(const float* __restrict__ Qm, const float* __restrict__ Km,
           const float* __restrict__ Vm, float* __restrict__ O) {
    __shared__ float Qs[64][64];
    __shared__ float Ks[32][68];
    __shared__ float Vs[32][64];
    __shared__ float Ps[64][33];

    const int bh = blockIdx.y;
    const int q0 = blockIdx.x * 64;
    const int tid = threadIdx.x;
    const int ty = tid >> 4;   // 0..15 : query group (4 queries)
    const int tx = tid & 15;   // 0..15 : kv-col / dim group

    const float* qb = Qm + (size_t)bh * SEQ * DHEAD;
    const float* kb = Km + (size_t)bh * SEQ * DHEAD;
    const float* vb = Vm + (size_t)bh * SEQ * DHEAD;

    // load Q tile (64x64), zero-pad beyond S
#pragma unroll
    for (int i = 0; i < 4; i++) {
        int idx = tid + i * 256;
        int row = idx >> 4;
        int c4 = (idx & 15) << 2;
        float4 val = make_float4(0.f, 0.f, 0.f, 0.f);
        if (q0 + row < SEQ) val = *reinterpret_cast<const float4*>(&qb[(size_t)(q0 + row) * DHEAD + c4]);
        *reinterpret_cast<float4*>(&Qs[row][c4]) = val;
    }

    float acc[4][4];
    float mi[4], li[4];
#pragma unroll
    for (int i = 0; i < 4; i++) {
        mi[i] = -1e30f;
        li[i] = 0.f;
#pragma unroll
        for (int j = 0; j < 4; j++) acc[i][j] = 0.f;
    }

    const int nkt = (SEQ + 31) / 32;
    for (int kt = 0; kt < nkt; kt++) {
        int k0 = kt * 32;
        // load K, V tiles (32x64)
#pragma unroll
        for (int i = 0; i < 2; i++) {
            int idx = tid + i * 256;
            int row = idx >> 4;
            int c4 = (idx & 15) << 2;
            float4 kv4 = make_float4(0.f, 0.f, 0.f, 0.f);
            float4 vv4 = make_float4(0.f, 0.f, 0.f, 0.f);
            if (k0 + row < SEQ) {
                kv4 = *reinterpret_cast<const float4*>(&kb[(size_t)(k0 + row) * DHEAD + c4]);
                vv4 = *reinterpret_cast<const float4*>(&vb[(size_t)(k0 + row) * DHEAD + c4]);
            }
            *reinterpret_cast<float4*>(&Ks[row][c4]) = kv4;
            *reinterpret_cast<float4*>(&Vs[row][c4]) = vv4;
        }
        __syncthreads();

        // S tile: queries 4*ty..+3  x  kv cols {2tx, 2tx+1}
        float s0[4], s1[4];
#pragma unroll
        for (int i = 0; i < 4; i++) { s0[i] = 0.f; s1[i] = 0.f; }
#pragma unroll 4
        for (int d4 = 0; d4 < 64; d4 += 4) {
            float4 kA = *reinterpret_cast<const float4*>(&Ks[2 * tx][d4]);
            float4 kB = *reinterpret_cast<const float4*>(&Ks[2 * tx + 1][d4]);
#pragma unroll
            for (int i = 0; i < 4; i++) {
                float4 qv = *reinterpret_cast<const float4*>(&Qs[4 * ty + i][d4]);
                s0[i] += qv.x * kA.x + qv.y * kA.y + qv.z * kA.z + qv.w * kA.w;
                s1[i] += qv.x * kB.x + qv.y * kB.y + qv.z * kB.z + qv.w * kB.w;
            }
        }

        bool ok0 = (k0 + 2 * tx) < SEQ;
        bool ok1 = (k0 + 2 * tx + 1) < SEQ;
#pragma unroll
        for (int i = 0; i < 4; i++) {
            float v0 = ok0 ? s0[i] : -1e30f;
            float v1 = ok1 ? s1[i] : -1e30f;
            float tm = fmaxf(v0, v1);
#pragma unroll
            for (int off = 8; off; off >>= 1)
                tm = fmaxf(tm, __shfl_xor_sync(0xffffffffu, tm, off));
            float mn = fmaxf(mi[i], tm);
            float alpha = __expf(mi[i] - mn);
            float p0 = ok0 ? __expf(s0[i] - mn) : 0.f;
            float p1 = ok1 ? __expf(s1[i] - mn) : 0.f;
            float rs = p0 + p1;
#pragma unroll
            for (int off = 8; off; off >>= 1)
                rs += __shfl_xor_sync(0xffffffffu, rs, off);
            li[i] = li[i] * alpha + rs;
            mi[i] = mn;
#pragma unroll
            for (int j = 0; j < 4; j++) acc[i][j] *= alpha;
            Ps[4 * ty + i][2 * tx] = p0;
            Ps[4 * ty + i][2 * tx + 1] = p1;
        }
        __syncthreads();

        // acc += P @ V : thread covers queries 4ty..+3, dims 4tx..+3
#pragma unroll 8
        for (int kv = 0; kv < 32; kv++) {
            float4 vv = *reinterpret_cast<const float4*>(&Vs[kv][4 * tx]);
#pragma unroll
            for (int i = 0; i < 4; i++) {
                float p = Ps[4 * ty + i][kv];
                acc[i][0] += p * vv.x;
                acc[i][1] += p * vv.y;
                acc[i][2] += p * vv.z;
                acc[i][3] += p * vv.w;
            }
        }
        __syncthreads();
    }

    // write merged output (B,S,D)
    const int b = bh >> 2;
    const int h = bh & 3;
#pragma unroll
    for (int i = 0; i < 4; i++) {
        int qrow = q0 + 4 * ty + i;
        if (qrow >= SEQ) continue;
        float inv = 1.f / li[i];
#pragma unroll
        for (int j = 0; j < 4; j++)
            O[((size_t)(b * SEQ + qrow)) * DMODEL + h * DHEAD + 4 * tx + j] = acc[i][j] * inv;
    }
}

// ---------------- residual + LayerNorm (R may be null) ----------------
__global__ void resid_ln(const float* __restrict__ X, const float* __restrict__ R,
                         const float* __restrict__ sc, const float* __restrict__ bi,
                         float* __restrict__ out) {
    int row = blockIdx.x;
    int d = threadIdx.x;  // 256
    size_t base = (size_t)row * DMODEL;
    float v = X[base + d];
    if (R) v += R[base + d];

    float s1 = v, s2 = v * v;
#pragma unroll
    for (int off = 16; off; off >>= 1) {
        s1 += __shfl_xor_sync(0xffffffffu, s1, off);
        s2 += __shfl_xor_sync(0xffffffffu, s2, off);
    }
    __shared__ float r1[8], r2[8];
    int warp = d >> 5, lane = d & 31;
    if (lane == 0) { r1[warp] = s1; r2[warp] = s2; }
    __syncthreads();
    if (d < 8) {
        float a = r1[d], b2 = r2[d];
#pragma unroll
        for (int off = 4; off; off >>= 1) {
            a += __shfl_xor_sync(0xffu, a, off);
            b2 += __shfl_xor_sync(0xffu, b2, off);
        }
        if (d == 0) { r1[0] = a; r2[0] = b2; }
    }
    __syncthreads();
    float mean = r1[0] * (1.f / DMODEL);
    float var = r2[0] * (1.f / DMODEL) - mean * mean;
    out[base + d] = (v - mean) * rsqrtf(var + LN_EPS) * sc[d] + bi[d];
}

// ---------------- partial mean over sequence ----------------
__global__ void mean_part(const float* __restrict__ Y, float* __restrict__ part) {
    int b = blockIdx.x;
    int c = blockIdx.y;      // 0..7
    int d = threadIdx.x;     // 0..255
    const int CH = (SEQ + 7) / 8;  // 422
    int s0 = c * CH;
    int s1 = min(SEQ, s0 + CH);
    float acc = 0.f;
    for (int s = s0; s < s1; s++)
        acc += Y[((size_t)b * SEQ + s) * DMODEL + d];
    part[(size_t)(b * 8 + c) * DMODEL + d] = acc;
}

// ---------------- classifier: logits[b,c] = mean(y[b]) . Wc[c] + bc[c] ----------------
__global__ void classifier(const float* __restrict__ part, const float* __restrict__ Wc,
                           const float* __restrict__ bc, float* __restrict__ out) {
    int t = threadIdx.x;      // 256
    int pair = t >> 5;        // 0..7 -> (b,c)
    int lane = t & 31;
    int b = pair >> 1, c = pair & 1;
    float acc = 0.f;
    for (int d = lane; d < DMODEL; d += 32) {
        float m = 0.f;
#pragma unroll
        for (int p = 0; p < 8; p++) m += part[(size_t)(b * 8 + p) * DMODEL + d];
        acc += m * Wc[c * DMODEL + d];
    }
#pragma unroll
    for (int off = 16; off; off >>= 1)
        acc += __shfl_xor_sync(0xffffffffu, acc, off);
    if (lane == 0) out[b * 2 + c] = acc * (1.f / SEQ) + bc[c];
}

// ---------------- launcher ----------------
static float* sym(const void* s) {
    void* p = nullptr;
    cudaGetSymbolAddress(&p, s);
    return (float*)p;
}

extern "C" void kernel_launch(void* const* d_in, const int* in_sizes, int n_in,
                              void* d_out, int out_size) {
    const int* C       = (const int*)d_in[0];
    const float* F     = (const float*)d_in[1];
    const float* W_fnn = (const float*)d_in[2];
    const float* b_fnn = (const float*)d_in[3];
    const float* in_w  = (const float*)d_in[4];
    const float* in_b  = (const float*)d_in[5];
    const float* out_w = (const float*)d_in[6];
    const float* out_b = (const float*)d_in[7];
    const float* ln1s  = (const float*)d_in[8];
    const float* ln1b  = (const float*)d_in[9];
    const float* W1    = (const float*)d_in[10];
    const float* b1    = (const float*)d_in[11];
    const float* W2    = (const float*)d_in[12];
    const float* b2    = (const float*)d_in[13];
    const float* ln2s  = (const float*)d_in[14];
    const float* ln2b  = (const float*)d_in[15];
    const float* ons   = (const float*)d_in[16];
    const float* onb   = (const float*)d_in[17];
    const float* Wc    = (const float*)d_in[18];
    const float* bc    = (const float*)d_in[19];
    float* out = (float*)d_out;

    float* pQ   = sym(g_Q);
    float* px   = sym(g_x);
    float* px2  = sym(g_x2);
    float* pqkv = sym(g_qkv);
    float* pq   = sym(g_q);
    float* pk   = sym(g_k);
    float* pv   = sym(g_v);
    float* po   = sym(g_o);
    float* pt   = sym(g_t);
    float* ph   = sym(g_h);
    float* py   = sym(g_y);
    float* ppart = sym(g_part);

    // 1) ROI embedding: Q = gelu(F @ W_fnn^T + b)   (6528 x 256, K=1632)
    {
        dim3 grid((DMODEL + BN - 1) / BN, (ROWS_Q + BM - 1) / BM);
        sgemm_nt<<<grid, 256>>>(F, W_fnn, b_fnn, pQ, ROWS_Q, DMODEL, DIN, 1);
    }
    // 2) gather + sum-pool -> tokens (B, S, D)
    {
        dim3 grid(SEQ, BATCH);
        gather_pool<<<grid, DMODEL>>>(pQ, C, px);
    }
    // 3) qkv projection (13500 x 768, K=256)
    {
        dim3 grid((3 * DMODEL + BN - 1) / BN, (ROWS_X + BM - 1) / BM);
        sgemm_nt<<<grid, 256>>>(px, in_w, in_b, pqkv, ROWS_X, 3 * DMODEL, DMODEL, 0);
    }
    // 4) split into heads (scale q)
    {
        int tot = ROWS_X * DMODEL;
        split_qkv<<<(tot + 255) / 256, 256>>>(pqkv, pq, pk, pv);
    }
    // 5) attention -> merged (B,S,D)
    {
        dim3 grid((SEQ + 63) / 64, BATCH * NHEAD);
        flash_attn<<<grid, 256>>>(pq, pk, pv, po);
    }
    // 6) out projection (13500 x 256, K=256)
    {
        dim3 grid((DMODEL + BN - 1) / BN, (ROWS_X + BM - 1) / BM);
        sgemm_nt<<<grid, 256>>>(po, out_w, out_b, pt, ROWS_X, DMODEL, DMODEL, 0);
    }
    // 7) x = LN(x + o)
    resid_ln<<<ROWS_X, DMODEL>>>(px, pt, ln1s, ln1b, px2);
    // 8) FFN1: h = gelu(x @ W1^T + b1)   (13500 x 1024, K=256)
    {
        dim3 grid((DFF + BN - 1) / BN, (ROWS_X + BM - 1) / BM);
        sgemm_nt<<<grid, 256>>>(px2, W1, b1, ph, ROWS_X, DFF, DMODEL, 1);
    }
    // 9) FFN2: t = h @ W2^T + b2   (13500 x 256, K=1024)
    {
        dim3 grid((DMODEL + BN - 1) / BN, (ROWS_X + BM - 1) / BM);
        sgemm_nt<<<grid, 256>>>(ph, W2, b2, pt, ROWS_X, DMODEL, DFF, 0);
    }
    // 10) x = LN(x + t)
    resid_ln<<<ROWS_X, DMODEL>>>(px2, pt, ln2s, ln2b, px);
    // 11) output norm
    resid_ln<<<ROWS_X, DMODEL>>>(px, nullptr, ons, onb, py);
    // 12) mean over sequence (two-stage, deterministic)
    {
        dim3 grid(BATCH, 8);
        mean_part<<<grid, DMODEL>>>(py, ppart);
    }
    // 13) classifier
    classifier<<<1, 256>>>(ppart, Wc, bc, out);
}

// round 2
// speedup vs baseline: 1.9367x; 1.9367x over previous
#include <cuda_runtime.h>
#include <cuda_bf16.h>
#include <math.h>

// ---------------- problem constants ----------------
#define BATCH 4
#define NROI 1632
#define DIN 1632
#define DMODEL 256
#define NHEAD 4
#define DHEAD 64
#define DFF 1024
#define SEQ 3375          // 15^3
#define ROWS_X (BATCH*SEQ)   // 13500
#define ROWS_Q (BATCH*NROI)  // 6528
#define LN_EPS 1e-5f

// ---------------- scratch (device globals; no allocation allowed) ----------------
__device__ float g_Q[ROWS_Q * DMODEL];
__device__ float g_x[ROWS_X * DMODEL];
__device__ float g_x2[ROWS_X * DMODEL];
__device__ float g_qkv[ROWS_X * 3 * DMODEL];
__device__ float g_q[BATCH * NHEAD * SEQ * DHEAD];
__device__ float g_k[BATCH * NHEAD * SEQ * DHEAD];
__device__ float g_v[BATCH * NHEAD * SEQ * DHEAD];
__device__ float g_o[ROWS_X * DMODEL];
__device__ float g_t[ROWS_X * DMODEL];
__device__ float g_h[ROWS_X * DFF];
__device__ float g_y[ROWS_X * DMODEL];
__device__ float g_part[BATCH * 8 * DMODEL];

// ---------------- helpers ----------------
__device__ __forceinline__ float gelu_exact(float x) {
    return 0.5f * x * (1.0f + erff(x * 0.70710678118654752f));
}
__device__ __forceinline__ float to_tf32(float x) {
    float r;
    asm("cvt.rna.tf32.f32 %0, %1;" : "=f"(r) : "f"(x));
    return r;
}
__device__ __forceinline__ void mma_tf32(float* d, const unsigned* a,
                                         unsigned b0, unsigned b1) {
    asm volatile(
        "mma.sync.aligned.m16n8k8.row.col.f32.tf32.tf32.f32 "
        "{%0,%1,%2,%3}, {%4,%5,%6,%7}, {%8,%9}, {%0,%1,%2,%3};\n"
        : "+f"(d[0]), "+f"(d[1]), "+f"(d[2]), "+f"(d[3])
        : "r"(a[0]), "r"(a[1]), "r"(a[2]), "r"(a[3]), "r"(b0), "r"(b1));
}

// ---------------- SGEMM: C[m,n] = act(sum_k A[m,k]*B[n,k] + bias[n]) ----------------
#define BM 128
#define BN 128
#define BK 8

__global__ void __launch_bounds__(256, 2)
sgemm_nt(const float* __restrict__ A, const float* __restrict__ B,
         const float* __restrict__ bias, float* __restrict__ C,
         int M, int N, int K, int act) {
    __shared__ float As[BK][BM];
    __shared__ float Bs[BK][BN];
    const int bm = blockIdx.y * BM;
    const int bn = blockIdx.x * BN;
    const int tid = threadIdx.x;
    const int ty = tid >> 4;
    const int tx = tid & 15;
    const int lrow = tid >> 1;
    const int lcol = (tid & 1) << 2;

    float acc[8][8];
#pragma unroll
    for (int i = 0; i < 8; i++)
#pragma unroll
        for (int j = 0; j < 8; j++) acc[i][j] = 0.f;

    for (int k0 = 0; k0 < K; k0 += BK) {
        float4 a4 = make_float4(0.f, 0.f, 0.f, 0.f);
        int ar = bm + lrow;
        if (ar < M) a4 = *reinterpret_cast<const float4*>(&A[(size_t)ar * K + k0 + lcol]);
        As[lcol + 0][lrow] = a4.x;
        As[lcol + 1][lrow] = a4.y;
        As[lcol + 2][lrow] = a4.z;
        As[lcol + 3][lrow] = a4.w;

        float4 b4 = make_float4(0.f, 0.f, 0.f, 0.f);
        int br = bn + lrow;
        if (br < N) b4 = *reinterpret_cast<const float4*>(&B[(size_t)br * K + k0 + lcol]);
        Bs[lcol + 0][lrow] = b4.x;
        Bs[lcol + 1][lrow] = b4.y;
        Bs[lcol + 2][lrow] = b4.z;
        Bs[lcol + 3][lrow] = b4.w;
        __syncthreads();

#pragma unroll
        for (int k = 0; k < BK; k++) {
            float ar_[8], br_[8];
#pragma unroll
            for (int i = 0; i < 8; i++) ar_[i] = As[k][ty * 8 + i];
#pragma unroll
            for (int j = 0; j < 8; j++) br_[j] = Bs[k][tx * 8 + j];
#pragma unroll
            for (int i = 0; i < 8; i++)
#pragma unroll
                for (int j = 0; j < 8; j++) acc[i][j] += ar_[i] * br_[j];
        }
        __syncthreads();
    }

#pragma unroll
    for (int i = 0; i < 8; i++) {
        int row = bm + ty * 8 + i;
        if (row >= M) continue;
#pragma unroll
        for (int j = 0; j < 8; j++) {
            int col = bn + tx * 8 + j;
            if (col >= N) continue;
            float vv = acc[i][j] + bias[col];
            if (act == 1) vv = gelu_exact(vv);
            C[(size_t)row * N + col] = vv;
        }
    }
}

// ---------------- gather + sum-pool ----------------
__global__ void gather_pool(const float* __restrict__ Q, const int* __restrict__ C,
                            float* __restrict__ out) {
    int o = blockIdx.x;
    int b = blockIdx.y;
    int d = threadIdx.x;
    int oz = o % 15;
    int oy = (o / 15) % 15;
    int ox = o / 225;
    const float* Qb = Q + (size_t)b * NROI * DMODEL;
    const int* Cb = C + (size_t)b * 32 * 32 * 32;
    float acc = 0.f;
#pragma unroll
    for (int dx = 0; dx < 3; dx++) {
        int x = 2 * ox + dx;
#pragma unroll
        for (int dy = 0; dy < 3; dy++) {
            int y = 2 * oy + dy;
#pragma unroll
            for (int dz = 0; dz < 3; dz++) {
                int z = 2 * oz + dz;
                int idx = Cb[(x * 32 + y) * 32 + z];
                acc += Qb[(size_t)idx * DMODEL + d];
            }
        }
    }
    out[((size_t)b * SEQ + o) * DMODEL + d] = acc;
}

// ---------------- split qkv into (B,H,S,DH), scale q by 1/8 ----------------
__global__ void split_qkv(const float* __restrict__ qkv, float* __restrict__ q,
                          float* __restrict__ k, float* __restrict__ v) {
    int t = blockIdx.x * blockDim.x + threadIdx.x;
    if (t >= ROWS_X * DMODEL) return;
    int d = t & 255;
    int s = (t >> 8) % SEQ;
    int b = t / (256 * SEQ);
    int h = d >> 6;
    int dh = d & 63;
    size_t src = (size_t)(b * SEQ + s) * (3 * DMODEL);
    size_t dst = ((size_t)(b * NHEAD + h) * SEQ + s) * DHEAD + dh;
    q[dst] = qkv[src + d] * 0.125f;
    k[dst] = qkv[src + DMODEL + d];
    v[dst] = qkv[src + 2 * DMODEL + d];
}

// ---------------- flash attention, tf32 mma.sync ----------------
// 128 threads (4 warps), 64-query tile per CTA (16 per warp), 64-key KV tiles.
// smem: Ks[64][68], Vs[64][72], Ps[64][68] (Ps doubles as Q staging).
#define KPAD 68
#define VPAD 72
#define FA_SMEM ((64*68 + 64*72 + 64*68) * 4)

__global__ void __launch_bounds__(128, 3)
flash_tf32(const float* __restrict__ Qm, const float* __restrict__ Km,
           const float* __restrict__ Vm, float* __restrict__ O) {
    extern __shared__ float sm[];
    float* Ks = sm;                       // [64][KPAD]
    float* Vs = sm + 64 * KPAD;           // [64][VPAD]
    float* Ps = sm + 64 * KPAD + 64 * VPAD; // [64][KPAD]

    const int bh = blockIdx.y;
    const int q0 = blockIdx.x * 64;
    const int tid = threadIdx.x;
    const int warp = tid >> 5;
    const int lane = tid & 31;
    const int g = lane >> 2;   // row group 0..7
    const int t = lane & 3;    // thread-in-group

    const float* qb = Qm + (size_t)bh * SEQ * DHEAD;
    const float* kb = Km + (size_t)bh * SEQ * DHEAD;
    const float* vb = Vm + (size_t)bh * SEQ * DHEAD;

    // stage Q tile (tf32-converted) into Ps
#pragma unroll
    for (int it = 0; it < 8; it++) {
        int idx = tid + it * 128;
        int row = idx >> 4;
        int c4 = (idx & 15) << 2;
        float4 v = make_float4(0.f, 0.f, 0.f, 0.f);
        if (q0 + row < SEQ) v = *reinterpret_cast<const float4*>(&qb[(size_t)(q0 + row) * 64 + c4]);
        v.x = to_tf32(v.x); v.y = to_tf32(v.y); v.z = to_tf32(v.z); v.w = to_tf32(v.w);
        *reinterpret_cast<float4*>(&Ps[row * KPAD + c4]) = v;
    }
    __syncthreads();

    const int pr = 16 * warp;
    unsigned qa[8][4];
#pragma unroll
    for (int kc = 0; kc < 8; kc++) {
        qa[kc][0] = __float_as_uint(Ps[(pr + g) * KPAD + kc * 8 + t]);
        qa[kc][1] = __float_as_uint(Ps[(pr + g + 8) * KPAD + kc * 8 + t]);
        qa[kc][2] = __float_as_uint(Ps[(pr + g) * KPAD + kc * 8 + t + 4]);
        qa[kc][3] = __float_as_uint(Ps[(pr + g + 8) * KPAD + kc * 8 + t + 4]);
    }
    // (no extra sync needed: each warp reads/writes only its own Ps rows from here on)

    float oc[8][4];
    float mi[2] = {-1e30f, -1e30f};
    float li[2] = {0.f, 0.f};
#pragma unroll
    for (int n = 0; n < 8; n++)
#pragma unroll
        for (int v = 0; v < 4; v++) oc[n][v] = 0.f;

    const int nkt = (SEQ + 63) / 64;
    for (int kt = 0; kt < nkt; kt++) {
        int k0 = kt * 64;
        // stage K, V tiles (tf32-converted)
#pragma unroll
        for (int it = 0; it < 8; it++) {
            int idx = tid + it * 128;
            int row = idx >> 4;
            int c4 = (idx & 15) << 2;
            float4 kv = make_float4(0.f, 0.f, 0.f, 0.f);
            float4 vv = make_float4(0.f, 0.f, 0.f, 0.f);
            if (k0 + row < SEQ) {
                kv = *reinterpret_cast<const float4*>(&kb[(size_t)(k0 + row) * 64 + c4]);
                vv = *reinterpret_cast<const float4*>(&vb[(size_t)(k0 + row) * 64 + c4]);
            }
            kv.x = to_tf32(kv.x); kv.y = to_tf32(kv.y); kv.z = to_tf32(kv.z); kv.w = to_tf32(kv.w);
            vv.x = to_tf32(vv.x); vv.y = to_tf32(vv.y); vv.z = to_tf32(vv.z); vv.w = to_tf32(vv.w);
            *reinterpret_cast<float4*>(&Ks[row * KPAD + c4]) = kv;
            *reinterpret_cast<float4*>(&Vs[row * VPAD + c4]) = vv;
        }
        __syncthreads();

        // S = Q K^T  (per warp: 16x64)
        float sf[8][4];
#pragma unroll
        for (int n = 0; n < 8; n++) {
            sf[n][0] = sf[n][1] = sf[n][2] = sf[n][3] = 0.f;
#pragma unroll
            for (int kc = 0; kc < 8; kc++) {
                unsigned b0 = __float_as_uint(Ks[(n * 8 + g) * KPAD + kc * 8 + t]);
                unsigned b1 = __float_as_uint(Ks[(n * 8 + g) * KPAD + kc * 8 + t + 4]);
                mma_tf32(sf[n], qa[kc], b0, b1);
            }
        }

        // mask out-of-range keys (last tile only)
        if (k0 + 64 > SEQ) {
            int lim = SEQ - k0;
#pragma unroll
            for (int n = 0; n < 8; n++) {
                int c0 = n * 8 + 2 * t;
                if (c0 >= lim) { sf[n][0] = -1e30f; sf[n][2] = -1e30f; }
                if (c0 + 1 >= lim) { sf[n][1] = -1e30f; sf[n][3] = -1e30f; }
            }
        }

        // online softmax (rows g and g+8; reduce over 4-lane group)
        float tm0 = -1e30f, tm1 = -1e30f;
#pragma unroll
        for (int n = 0; n < 8; n++) {
            tm0 = fmaxf(tm0, fmaxf(sf[n][0], sf[n][1]));
            tm1 = fmaxf(tm1, fmaxf(sf[n][2], sf[n][3]));
        }
        tm0 = fmaxf(tm0, __shfl_xor_sync(0xffffffffu, tm0, 1));
        tm0 = fmaxf(tm0, __shfl_xor_sync(0xffffffffu, tm0, 2));
        tm1 = fmaxf(tm1, __shfl_xor_sync(0xffffffffu, tm1, 1));
        tm1 = fmaxf(tm1, __shfl_xor_sync(0xffffffffu, tm1, 2));
        float mn0 = fmaxf(mi[0], tm0);
        float mn1 = fmaxf(mi[1], tm1);
        float a0 = __expf(mi[0] - mn0);
        float a1 = __expf(mi[1] - mn1);
        float rs0 = 0.f, rs1 = 0.f;
#pragma unroll
        for (int n = 0; n < 8; n++) {
            float p0 = __expf(sf[n][0] - mn0);
            float p1 = __expf(sf[n][1] - mn0);
            float p2 = __expf(sf[n][2] - mn1);
            float p3 = __expf(sf[n][3] - mn1);
            rs0 += p0 + p1;
            rs1 += p2 + p3;
            float2 lo = make_float2(to_tf32(p0), to_tf32(p1));
            float2 hi = make_float2(to_tf32(p2), to_tf32(p3));
            *reinterpret_cast<float2*>(&Ps[(pr + g) * KPAD + n * 8 + 2 * t]) = lo;
            *reinterpret_cast<float2*>(&Ps[(pr + g + 8) * KPAD + n * 8 + 2 * t]) = hi;
        }
        rs0 += __shfl_xor_sync(0xffffffffu, rs0, 1);
        rs0 += __shfl_xor_sync(0xffffffffu, rs0, 2);
        rs1 += __shfl_xor_sync(0xffffffffu, rs1, 1);
        rs1 += __shfl_xor_sync(0xffffffffu, rs1, 2);
        li[0] = li[0] * a0 + rs0;
        li[1] = li[1] * a1 + rs1;
        mi[0] = mn0;
        mi[1] = mn1;
#pragma unroll
        for (int n = 0; n < 8; n++) {
            oc[n][0] *= a0; oc[n][1] *= a0;
            oc[n][2] *= a1; oc[n][3] *= a1;
        }
        __syncwarp();

        // O += P V  (per warp: 16x64)
#pragma unroll
        for (int kc = 0; kc < 8; kc++) {
            unsigned pa[4];
            pa[0] = __float_as_uint(Ps[(pr + g) * KPAD + kc * 8 + t]);
            pa[1] = __float_as_uint(Ps[(pr + g + 8) * KPAD + kc * 8 + t]);
            pa[2] = __float_as_uint(Ps[(pr + g) * KPAD + kc * 8 + t + 4]);
            pa[3] = __float_as_uint(Ps[(pr + g + 8) * KPAD + kc * 8 + t + 4]);
#pragma unroll
            for (int n = 0; n < 8; n++) {
                unsigned b0 = __float_as_uint(Vs[(kc * 8 + t) * VPAD + n * 8 + g]);
                unsigned b1 = __float_as_uint(Vs[(kc * 8 + t + 4) * VPAD + n * 8 + g]);
                mma_tf32(oc[n], pa, b0, b1);
            }
        }
        __syncthreads();
    }

    // epilogue: normalize + write merged (B,S,D)
    const int b = bh >> 2;
    const int h = bh & 3;
    float inv0 = 1.f / li[0];
    float inv1 = 1.f / li[1];
    int qr0 = q0 + pr + g;
    int qr1 = qr0 + 8;
#pragma unroll
    for (int n = 0; n < 8; n++) {
        int d = h * 64 + n * 8 + 2 * t;
        if (qr0 < SEQ) {
            float2 o2 = make_float2(oc[n][0] * inv0, oc[n][1] * inv0);
            *reinterpret_cast<float2*>(&O[((size_t)(b * SEQ + qr0)) * DMODEL + d]) = o2;
        }
        if (qr1 < SEQ) {
            float2 o2 = make_float2(oc[n][2] * inv1, oc[n][3] * inv1);
            *reinterpret_cast<float2*>(&O[((size_t)(b * SEQ + qr1)) * DMODEL + d]) = o2;
        }
    }
}

// ---------------- residual + LayerNorm (R may be null) ----------------
__global__ void resid_ln(const float* __restrict__ X, const float* __restrict__ R,
                         const float* __restrict__ sc, const float* __restrict__ bi,
                         float* __restrict__ out) {
    int row = blockIdx.x;
    int d = threadIdx.x;
    size_t base = (size_t)row * DMODEL;
    float v = X[base + d];
    if (R) v += R[base + d];

    float s1 = v, s2 = v * v;
#pragma unroll
    for (int off = 16; off; off >>= 1) {
        s1 += __shfl_xor_sync(0xffffffffu, s1, off);
        s2 += __shfl_xor_sync(0xffffffffu, s2, off);
    }
    __shared__ float r1[8], r2[8];
    int warp = d >> 5, lane = d & 31;
    if (lane == 0) { r1[warp] = s1; r2[warp] = s2; }
    __syncthreads();
    if (d < 8) {
        float a = r1[d], b2 = r2[d];
#pragma unroll
        for (int off = 4; off; off >>= 1) {
            a += __shfl_xor_sync(0xffu, a, off);
            b2 += __shfl_xor_sync(0xffu, b2, off);
        }
        if (d == 0) { r1[0] = a; r2[0] = b2; }
    }
    __syncthreads();
    float mean = r1[0] * (1.f / DMODEL);
    float var = r2[0] * (1.f / DMODEL) - mean * mean;
    out[base + d] = (v - mean) * rsqrtf(var + LN_EPS) * sc[d] + bi[d];
}

// ---------------- partial mean over sequence ----------------
__global__ void mean_part(const float* __restrict__ Y, float* __restrict__ part) {
    int b = blockIdx.x;
    int c = blockIdx.y;
    int d = threadIdx.x;
    const int CH = (SEQ + 7) / 8;
    int s0 = c * CH;
    int s1 = min(SEQ, s0 + CH);
    float acc = 0.f;
    for (int s = s0; s < s1; s++)
        acc += Y[((size_t)b * SEQ + s) * DMODEL + d];
    part[(size_t)(b * 8 + c) * DMODEL + d] = acc;
}

// ---------------- classifier ----------------
__global__ void classifier(const float* __restrict__ part, const float* __restrict__ Wc,
                           const float* __restrict__ bc, float* __restrict__ out) {
    int t = threadIdx.x;
    int pair = t >> 5;
    int lane = t & 31;
    int b = pair >> 1, c = pair & 1;
    float acc = 0.f;
    for (int d = lane; d < DMODEL; d += 32) {
        float m = 0.f;
#pragma unroll
        for (int p = 0; p < 8; p++) m += part[(size_t)(b * 8 + p) * DMODEL + d];
        acc += m * Wc[c * DMODEL + d];
    }
#pragma unroll
    for (int off = 16; off; off >>= 1)
        acc += __shfl_xor_sync(0xffffffffu, acc, off);
    if (lane == 0) out[b * 2 + c] = acc * (1.f / SEQ) + bc[c];
}

// ---------------- launcher ----------------
static float* sym(const void* s) {
    void* p = nullptr;
    cudaGetSymbolAddress(&p, s);
    return (float*)p;
}

extern "C" void kernel_launch(void* const* d_in, const int* in_sizes, int n_in,
                              void* d_out, int out_size) {
    const int* C       = (const int*)d_in[0];
    const float* F     = (const float*)d_in[1];
    const float* W_fnn = (const float*)d_in[2];
    const float* b_fnn = (const float*)d_in[3];
    const float* in_w  = (const float*)d_in[4];
    const float* in_b  = (const float*)d_in[5];
    const float* out_w = (const float*)d_in[6];
    const float* out_b = (const float*)d_in[7];
    const float* ln1s  = (const float*)d_in[8];
    const float* ln1b  = (const float*)d_in[9];
    const float* W1    = (const float*)d_in[10];
    const float* b1    = (const float*)d_in[11];
    const float* W2    = (const float*)d_in[12];
    const float* b2    = (const float*)d_in[13];
    const float* ln2s  = (const float*)d_in[14];
    const float* ln2b  = (const float*)d_in[15];
    const float* ons   = (const float*)d_in[16];
    const float* onb   = (const float*)d_in[17];
    const float* Wc    = (const float*)d_in[18];
    const float* bc    = (const float*)d_in[19];
    float* out = (float*)d_out;

    float* pQ    = sym(g_Q);
    float* px    = sym(g_x);
    float* px2   = sym(g_x2);
    float* pqkv  = sym(g_qkv);
    float* pq    = sym(g_q);
    float* pk    = sym(g_k);
    float* pv    = sym(g_v);
    float* po    = sym(g_o);
    float* pt    = sym(g_t);
    float* ph    = sym(g_h);
    float* py    = sym(g_y);
    float* ppart = sym(g_part);

    cudaFuncSetAttribute(flash_tf32, cudaFuncAttributeMaxDynamicSharedMemorySize, FA_SMEM);

    // 1) ROI embedding: Q = gelu(F @ W_fnn^T + b)
    {
        dim3 grid((DMODEL + BN - 1) / BN, (ROWS_Q + BM - 1) / BM);
        sgemm_nt<<<grid, 256>>>(F, W_fnn, b_fnn, pQ, ROWS_Q, DMODEL, DIN, 1);
    }
    // 2) gather + sum-pool -> tokens
    {
        dim3 grid(SEQ, BATCH);
        gather_pool<<<grid, DMODEL>>>(pQ, C, px);
    }
    // 3) qkv projection
    {
        dim3 grid((3 * DMODEL + BN - 1) / BN, (ROWS_X + BM - 1) / BM);
        sgemm_nt<<<grid, 256>>>(px, in_w, in_b, pqkv, ROWS_X, 3 * DMODEL, DMODEL, 0);
    }
    // 4) split into heads (scale q)
    {
        int tot = ROWS_X * DMODEL;
        split_qkv<<<(tot + 255) / 256, 256>>>(pqkv, pq, pk, pv);
    }
    // 5) attention (tf32 tensor-core flash)
    {
        dim3 grid((SEQ + 63) / 64, BATCH * NHEAD);
        flash_tf32<<<grid, 128, FA_SMEM>>>(pq, pk, pv, po);
    }
    // 6) out projection
    {
        dim3 grid((DMODEL + BN - 1) / BN, (ROWS_X + BM - 1) / BM);
        sgemm_nt<<<grid, 256>>>(po, out_w, out_b, pt, ROWS_X, DMODEL, DMODEL, 0);
    }
    // 7) x = LN(x + o)
    resid_ln<<<ROWS_X, DMODEL>>>(px, pt, ln1s, ln1b, px2);
    // 8) FFN1
    {
        dim3 grid((DFF + BN - 1) / BN, (ROWS_X + BM - 1) / BM);
        sgemm_nt<<<grid, 256>>>(px2, W1, b1, ph, ROWS_X, DFF, DMODEL, 1);
    }
    // 9) FFN2
    {
        dim3 grid((DMODEL + BN - 1) / BN, (ROWS_X + BM - 1) / BM);
        sgemm_nt<<<grid, 256>>>(ph, W2, b2, pt, ROWS_X, DMODEL, DFF, 0);
    }
    // 10) x = LN(x + t)
    resid_ln<<<ROWS_X, DMODEL>>>(px2, pt, ln2s, ln2b, px);
    // 11) output norm
    resid_ln<<<ROWS_X, DMODEL>>>(px, nullptr, ons, onb, py);
    // 12) mean over sequence
    {
        dim3 grid(BATCH, 8);
        mean_part<<<grid, DMODEL>>>(py, ppart);
    }
    // 13) classifier
    classifier<<<1, 256>>>(ppart, Wc, bc, out);
}

// round 3
// speedup vs baseline: 1.9881x; 1.0265x over previous
#include <cuda_runtime.h>
#include <cuda_bf16.h>
#include <math.h>

// ---------------- problem constants ----------------
#define BATCH 4
#define NROI 1632
#define DIN 1632
#define DMODEL 256
#define NHEAD 4
#define DHEAD 64
#define DFF 1024
#define SEQ 3375          // 15^3
#define ROWS_X (BATCH*SEQ)   // 13500
#define ROWS_Q (BATCH*NROI)  // 6528
#define LN_EPS 1e-5f

// ---------------- scratch (device globals; no allocation allowed) ----------------
__device__ float g_Q[ROWS_Q * DMODEL];
__device__ float g_x[ROWS_X * DMODEL];
__device__ float g_x2[ROWS_X * DMODEL];
__device__ float g_q[BATCH * NHEAD * SEQ * DHEAD];
__device__ float g_k[BATCH * NHEAD * SEQ * DHEAD];
__device__ float g_v[BATCH * NHEAD * SEQ * DHEAD];
__device__ float g_o[ROWS_X * DMODEL];
__device__ float g_t[ROWS_X * DMODEL];
__device__ float g_h[ROWS_X * DFF];
__device__ float g_y[ROWS_X * DMODEL];
__device__ float g_part[BATCH * 8 * DMODEL];

// ---------------- helpers ----------------
__device__ __forceinline__ float gelu_exact(float x) {
    return 0.5f * x * (1.0f + erff(x * 0.70710678118654752f));
}
__device__ __forceinline__ float to_tf32(float x) {
    float r;
    asm("cvt.rna.tf32.f32 %0, %1;" : "=f"(r) : "f"(x));
    return r;
}
__device__ __forceinline__ void mma_tf32(float* d, const unsigned* a,
                                         unsigned b0, unsigned b1) {
    asm volatile(
        "mma.sync.aligned.m16n8k8.row.col.f32.tf32.tf32.f32 "
        "{%0,%1,%2,%3}, {%4,%5,%6,%7}, {%8,%9}, {%0,%1,%2,%3};\n"
        : "+f"(d[0]), "+f"(d[1]), "+f"(d[2]), "+f"(d[3])
        : "r"(a[0]), "r"(a[1]), "r"(a[2]), "r"(a[3]), "r"(b0), "r"(b1));
}
// packed fp32x2 FMA (Blackwell): d = a*b + d elementwise on 2 lanes
__device__ __forceinline__ void ffma2(unsigned long long& d,
                                      unsigned long long a, unsigned long long b) {
    asm("fma.rn.f32x2 %0, %1, %2, %0;" : "+l"(d) : "l"(a), "l"(b));
}
__device__ __forceinline__ unsigned long long pack2(float x, float y) {
    unsigned long long r;
    asm("mov.b64 %0, {%1, %2};" : "=l"(r) : "f"(x), "f"(y));
    return r;
}
__device__ __forceinline__ void unpack2(float& x, float& y, unsigned long long v) {
    asm("mov.b64 {%0, %1}, %2;" : "=f"(x), "=f"(y) : "l"(v));
}

// ---------------- SGEMM: C[m,n] = act(sum_k A[m,k]*B[n,k] + bias[n]) ----------------
// BM=BN=128, BK=8, 256 threads, 8x8 microtile via packed f32x2 FMA.
// act: 0 = none, 1 = gelu, 2 = qkv-split epilogue (C unused; writes qp/kp/vp).
#define BM 128
#define BN 128
#define BK 8

__global__ void __launch_bounds__(256, 2)
sgemm_nt(const float* __restrict__ A, const float* __restrict__ B,
         const float* __restrict__ bias, float* __restrict__ C,
         int M, int N, int K, int act,
         float* __restrict__ qp, float* __restrict__ kp, float* __restrict__ vp) {
    __shared__ float As[BK][BM];
    __shared__ float Bs[BK][BN];
    const int bm = blockIdx.y * BM;
    const int bn = blockIdx.x * BN;
    const int tid = threadIdx.x;
    const int ty = tid >> 4;
    const int tx = tid & 15;
    const int lrow = tid >> 1;
    const int lcol = (tid & 1) << 2;

    unsigned long long acc2[8][4];
#pragma unroll
    for (int i = 0; i < 8; i++)
#pragma unroll
        for (int j = 0; j < 4; j++) acc2[i][j] = 0ull;

    for (int k0 = 0; k0 < K; k0 += BK) {
        float4 a4 = make_float4(0.f, 0.f, 0.f, 0.f);
        int ar = bm + lrow;
        if (ar < M) a4 = *reinterpret_cast<const float4*>(&A[(size_t)ar * K + k0 + lcol]);
        As[lcol + 0][lrow] = a4.x;
        As[lcol + 1][lrow] = a4.y;
        As[lcol + 2][lrow] = a4.z;
        As[lcol + 3][lrow] = a4.w;

        float4 b4 = make_float4(0.f, 0.f, 0.f, 0.f);
        int br = bn + lrow;
        if (br < N) b4 = *reinterpret_cast<const float4*>(&B[(size_t)br * K + k0 + lcol]);
        Bs[lcol + 0][lrow] = b4.x;
        Bs[lcol + 1][lrow] = b4.y;
        Bs[lcol + 2][lrow] = b4.z;
        Bs[lcol + 3][lrow] = b4.w;
        __syncthreads();

#pragma unroll
        for (int k = 0; k < BK; k++) {
            // b pairs: 4 x f32x2 (contiguous in smem)
            unsigned long long b2[4];
            float4 bl = *reinterpret_cast<const float4*>(&Bs[k][tx * 8]);
            float4 bh = *reinterpret_cast<const float4*>(&Bs[k][tx * 8 + 4]);
            b2[0] = pack2(bl.x, bl.y);
            b2[1] = pack2(bl.z, bl.w);
            b2[2] = pack2(bh.x, bh.y);
            b2[3] = pack2(bh.z, bh.w);
            float4 al = *reinterpret_cast<const float4*>(&As[k][ty * 8]);
            float4 ah = *reinterpret_cast<const float4*>(&As[k][ty * 8 + 4]);
            float a_[8] = {al.x, al.y, al.z, al.w, ah.x, ah.y, ah.z, ah.w};
#pragma unroll
            for (int i = 0; i < 8; i++) {
                unsigned long long ad = pack2(a_[i], a_[i]);
                ffma2(acc2[i][0], ad, b2[0]);
                ffma2(acc2[i][1], ad, b2[1]);
                ffma2(acc2[i][2], ad, b2[2]);
                ffma2(acc2[i][3], ad, b2[3]);
            }
        }
        __syncthreads();
    }

    // bias for this thread's 8 columns
    float bi[8];
#pragma unroll
    for (int j = 0; j < 8; j++) {
        int col = bn + tx * 8 + j;
        bi[j] = (col < N) ? bias[col] : 0.f;
    }

    if (act != 2) {
#pragma unroll
        for (int i = 0; i < 8; i++) {
            int row = bm + ty * 8 + i;
            if (row >= M) continue;
            float r[8];
#pragma unroll
            for (int j = 0; j < 4; j++) unpack2(r[2 * j], r[2 * j + 1], acc2[i][j]);
#pragma unroll
            for (int j = 0; j < 8; j++) {
                int col = bn + tx * 8 + j;
                if (col >= N) continue;
                float vv = r[j] + bi[j];
                if (act == 1) vv = gelu_exact(vv);
                C[(size_t)row * N + col] = vv;
            }
        }
    } else {
        // qkv-split epilogue: N=768. cols [0,256)=q, [256,512)=k, [512,768)=v.
        // Each 8-col chunk stays inside one section and one head (all boundaries % 8 == 0).
        int c0 = bn + tx * 8;
        int sec = c0 >> 8;           // 0,1,2
        int d = c0 & 255;
        int h = d >> 6;
        int dh0 = d & 63;            // aligned to 8
        float* dst = (sec == 0) ? qp : (sec == 1) ? kp : vp;
        float scale = (sec == 0) ? 0.125f : 1.f;
#pragma unroll
        for (int i = 0; i < 8; i++) {
            int row = bm + ty * 8 + i;
            if (row >= M) continue;
            int b = row / SEQ;
            int s = row - b * SEQ;
            float r[8];
#pragma unroll
            for (int j = 0; j < 4; j++) unpack2(r[2 * j], r[2 * j + 1], acc2[i][j]);
            float4 lo = make_float4((r[0] + bi[0]) * scale, (r[1] + bi[1]) * scale,
                                    (r[2] + bi[2]) * scale, (r[3] + bi[3]) * scale);
            float4 hi = make_float4((r[4] + bi[4]) * scale, (r[5] + bi[5]) * scale,
                                    (r[6] + bi[6]) * scale, (r[7] + bi[7]) * scale);
            size_t base = ((size_t)(b * NHEAD + h) * SEQ + s) * DHEAD + dh0;
            *reinterpret_cast<float4*>(&dst[base]) = lo;
            *reinterpret_cast<float4*>(&dst[base + 4]) = hi;
        }
    }
}

// ---------------- gather + sum-pool ----------------
__global__ void gather_pool(const float* __restrict__ Q, const int* __restrict__ C,
                            float* __restrict__ out) {
    int o = blockIdx.x;
    int b = blockIdx.y;
    int d = threadIdx.x;
    int oz = o % 15;
    int oy = (o / 15) % 15;
    int ox = o / 225;
    const float* Qb = Q + (size_t)b * NROI * DMODEL;
    const int* Cb = C + (size_t)b * 32 * 32 * 32;
    float acc = 0.f;
#pragma unroll
    for (int dx = 0; dx < 3; dx++) {
        int x = 2 * ox + dx;
#pragma unroll
        for (int dy = 0; dy < 3; dy++) {
            int y = 2 * oy + dy;
#pragma unroll
            for (int dz = 0; dz < 3; dz++) {
                int z = 2 * oz + dz;
                int idx = Cb[(x * 32 + y) * 32 + z];
                acc += Qb[(size_t)idx * DMODEL + d];
            }
        }
    }
    out[((size_t)b * SEQ + o) * DMODEL + d] = acc;
}

// ---------------- flash attention, tf32 mma.sync ----------------
#define KPAD 68
#define VPAD 72
#define FA_SMEM ((64*68 + 64*72 + 64*68) * 4)

__global__ void __launch_bounds__(128, 3)
flash_tf32(const float* __restrict__ Qm, const float* __restrict__ Km,
           const float* __restrict__ Vm, float* __restrict__ O) {
    extern __shared__ float sm[];
    float* Ks = sm;
    float* Vs = sm + 64 * KPAD;
    float* Ps = sm + 64 * KPAD + 64 * VPAD;

    const int bh = blockIdx.y;
    const int q0 = blockIdx.x * 64;
    const int tid = threadIdx.x;
    const int warp = tid >> 5;
    const int lane = tid & 31;
    const int g = lane >> 2;
    const int t = lane & 3;

    const float* qb = Qm + (size_t)bh * SEQ * DHEAD;
    const float* kb = Km + (size_t)bh * SEQ * DHEAD;
    const float* vb = Vm + (size_t)bh * SEQ * DHEAD;

#pragma unroll
    for (int it = 0; it < 8; it++) {
        int idx = tid + it * 128;
        int row = idx >> 4;
        int c4 = (idx & 15) << 2;
        float4 v = make_float4(0.f, 0.f, 0.f, 0.f);
        if (q0 + row < SEQ) v = *reinterpret_cast<const float4*>(&qb[(size_t)(q0 + row) * 64 + c4]);
        v.x = to_tf32(v.x); v.y = to_tf32(v.y); v.z = to_tf32(v.z); v.w = to_tf32(v.w);
        *reinterpret_cast<float4*>(&Ps[row * KPAD + c4]) = v;
    }
    __syncthreads();

    const int pr = 16 * warp;
    unsigned qa[8][4];
#pragma unroll
    for (int kc = 0; kc < 8; kc++) {
        qa[kc][0] = __float_as_uint(Ps[(pr + g) * KPAD + kc * 8 + t]);
        qa[kc][1] = __float_as_uint(Ps[(pr + g + 8) * KPAD + kc * 8 + t]);
        qa[kc][2] = __float_as_uint(Ps[(pr + g) * KPAD + kc * 8 + t + 4]);
        qa[kc][3] = __float_as_uint(Ps[(pr + g + 8) * KPAD + kc * 8 + t + 4]);
    }

    float oc[8][4];
    float mi[2] = {-1e30f, -1e30f};
    float li[2] = {0.f, 0.f};
#pragma unroll
    for (int n = 0; n < 8; n++)
#pragma unroll
        for (int v = 0; v < 4; v++) oc[n][v] = 0.f;

    const int nkt = (SEQ + 63) / 64;
    for (int kt = 0; kt < nkt; kt++) {
        int k0 = kt * 64;
#pragma unroll
        for (int it = 0; it < 8; it++) {
            int idx = tid + it * 128;
            int row = idx >> 4;
            int c4 = (idx & 15) << 2;
            float4 kv = make_float4(0.f, 0.f, 0.f, 0.f);
            float4 vv = make_float4(0.f, 0.f, 0.f, 0.f);
            if (k0 + row < SEQ) {
                kv = *reinterpret_cast<const float4*>(&kb[(size_t)(k0 + row) * 64 + c4]);
                vv = *reinterpret_cast<const float4*>(&vb[(size_t)(k0 + row) * 64 + c4]);
            }
            kv.x = to_tf32(kv.x); kv.y = to_tf32(kv.y); kv.z = to_tf32(kv.z); kv.w = to_tf32(kv.w);
            vv.x = to_tf32(vv.x); vv.y = to_tf32(vv.y); vv.z = to_tf32(vv.z); vv.w = to_tf32(vv.w);
            *reinterpret_cast<float4*>(&Ks[row * KPAD + c4]) = kv;
            *reinterpret_cast<float4*>(&Vs[row * VPAD + c4]) = vv;
        }
        __syncthreads();

        float sf[8][4];
#pragma unroll
        for (int n = 0; n < 8; n++) {
            sf[n][0] = sf[n][1] = sf[n][2] = sf[n][3] = 0.f;
#pragma unroll
            for (int kc = 0; kc < 8; kc++) {
                unsigned b0 = __float_as_uint(Ks[(n * 8 + g) * KPAD + kc * 8 + t]);
                unsigned b1 = __float_as_uint(Ks[(n * 8 + g) * KPAD + kc * 8 + t + 4]);
                mma_tf32(sf[n], qa[kc], b0, b1);
            }
        }

        if (k0 + 64 > SEQ) {
            int lim = SEQ - k0;
#pragma unroll
            for (int n = 0; n < 8; n++) {
                int c0 = n * 8 + 2 * t;
                if (c0 >= lim) { sf[n][0] = -1e30f; sf[n][2] = -1e30f; }
                if (c0 + 1 >= lim) { sf[n][1] = -1e30f; sf[n][3] = -1e30f; }
            }
        }

        float tm0 = -1e30f, tm1 = -1e30f;
#pragma unroll
        for (int n = 0; n < 8; n++) {
            tm0 = fmaxf(tm0, fmaxf(sf[n][0], sf[n][1]));
            tm1 = fmaxf(tm1, fmaxf(sf[n][2], sf[n][3]));
        }
        tm0 = fmaxf(tm0, __shfl_xor_sync(0xffffffffu, tm0, 1));
        tm0 = fmaxf(tm0, __shfl_xor_sync(0xffffffffu, tm0, 2));
        tm1 = fmaxf(tm1, __shfl_xor_sync(0xffffffffu, tm1, 1));
        tm1 = fmaxf(tm1, __shfl_xor_sync(0xffffffffu, tm1, 2));
        float mn0 = fmaxf(mi[0], tm0);
        float mn1 = fmaxf(mi[1], tm1);
        float a0 = __expf(mi[0] - mn0);
        float a1 = __expf(mi[1] - mn1);
        float rs0 = 0.f, rs1 = 0.f;
#pragma unroll
        for (int n = 0; n < 8; n++) {
            float p0 = __expf(sf[n][0] - mn0);
            float p1 = __expf(sf[n][1] - mn0);
            float p2 = __expf(sf[n][2] - mn1);
            float p3 = __expf(sf[n][3] - mn1);
            rs0 += p0 + p1;
            rs1 += p2 + p3;
            float2 lo = make_float2(to_tf32(p0), to_tf32(p1));
            float2 hi = make_float2(to_tf32(p2), to_tf32(p3));
            *reinterpret_cast<float2*>(&Ps[(pr + g) * KPAD + n * 8 + 2 * t]) = lo;
            *reinterpret_cast<float2*>(&Ps[(pr + g + 8) * KPAD + n * 8 + 2 * t]) = hi;
        }
        rs0 += __shfl_xor_sync(0xffffffffu, rs0, 1);
        rs0 += __shfl_xor_sync(0xffffffffu, rs0, 2);
        rs1 += __shfl_xor_sync(0xffffffffu, rs1, 1);
        rs1 += __shfl_xor_sync(0xffffffffu, rs1, 2);
        li[0] = li[0] * a0 + rs0;
        li[1] = li[1] * a1 + rs1;
        mi[0] = mn0;
        mi[1] = mn1;
#pragma unroll
        for (int n = 0; n < 8; n++) {
            oc[n][0] *= a0; oc[n][1] *= a0;
            oc[n][2] *= a1; oc[n][3] *= a1;
        }
        __syncwarp();

#pragma unroll
        for (int kc = 0; kc < 8; kc++) {
            unsigned pa[4];
            pa[0] = __float_as_uint(Ps[(pr + g) * KPAD + kc * 8 + t]);
            pa[1] = __float_as_uint(Ps[(pr + g + 8) * KPAD + kc * 8 + t]);
            pa[2] = __float_as_uint(Ps[(pr + g) * KPAD + kc * 8 + t + 4]);
            pa[3] = __float_as_uint(Ps[(pr + g + 8) * KPAD + kc * 8 + t + 4]);
#pragma unroll
            for (int n = 0; n < 8; n++) {
                unsigned b0 = __float_as_uint(Vs[(kc * 8 + t) * VPAD + n * 8 + g]);
                unsigned b1 = __float_as_uint(Vs[(kc * 8 + t + 4) * VPAD + n * 8 + g]);
                mma_tf32(oc[n], pa, b0, b1);
            }
        }
        __syncthreads();
    }

    const int b = bh >> 2;
    const int h = bh & 3;
    float inv0 = 1.f / li[0];
    float inv1 = 1.f / li[1];
    int qr0 = q0 + pr + g;
    int qr1 = qr0 + 8;
#pragma unroll
    for (int n = 0; n < 8; n++) {
        int d = h * 64 + n * 8 + 2 * t;
        if (qr0 < SEQ) {
            float2 o2 = make_float2(oc[n][0] * inv0, oc[n][1] * inv0);
            *reinterpret_cast<float2*>(&O[((size_t)(b * SEQ + qr0)) * DMODEL + d]) = o2;
        }
        if (qr1 < SEQ) {
            float2 o2 = make_float2(oc[n][2] * inv1, oc[n][3] * inv1);
            *reinterpret_cast<float2*>(&O[((size_t)(b * SEQ + qr1)) * DMODEL + d]) = o2;
        }
    }
}

// ---------------- residual + LayerNorm (R may be null) ----------------
__global__ void resid_ln(const float* __restrict__ X, const float* __restrict__ R,
                         const float* __restrict__ sc, const float* __restrict__ bi,
                         float* __restrict__ out) {
    int row = blockIdx.x;
    int d = threadIdx.x;
    size_t base = (size_t)row * DMODEL;
    float v = X[base + d];
    if (R) v += R[base + d];

    float s1 = v, s2 = v * v;
#pragma unroll
    for (int off = 16; off; off >>= 1) {
        s1 += __shfl_xor_sync(0xffffffffu, s1, off);
        s2 += __shfl_xor_sync(0xffffffffu, s2, off);
    }
    __shared__ float r1[8], r2[8];
    int warp = d >> 5, lane = d & 31;
    if (lane == 0) { r1[warp] = s1; r2[warp] = s2; }
    __syncthreads();
    if (d < 8) {
        float a = r1[d], b2 = r2[d];
#pragma unroll
        for (int off = 4; off; off >>= 1) {
            a += __shfl_xor_sync(0xffu, a, off);
            b2 += __shfl_xor_sync(0xffu, b2, off);
        }
        if (d == 0) { r1[0] = a; r2[0] = b2; }
    }
    __syncthreads();
    float mean = r1[0] * (1.f / DMODEL);
    float var = r2[0] * (1.f / DMODEL) - mean * mean;
    out[base + d] = (v - mean) * rsqrtf(var + LN_EPS) * sc[d] + bi[d];
}

// ---------------- partial mean over sequence ----------------
__global__ void mean_part(const float* __restrict__ Y, float* __restrict__ part) {
    int b = blockIdx.x;
    int c = blockIdx.y;
    int d = threadIdx.x;
    const int CH = (SEQ + 7) / 8;
    int s0 = c * CH;
    int s1 = min(SEQ, s0 + CH);
    float acc = 0.f;
    for (int s = s0; s < s1; s++)
        acc += Y[((size_t)b * SEQ + s) * DMODEL + d];
    part[(size_t)(b * 8 + c) * DMODEL + d] = acc;
}

// ---------------- classifier ----------------
__global__ void classifier(const float* __restrict__ part, const float* __restrict__ Wc,
                           const float* __restrict__ bc, float* __restrict__ out) {
    int t = threadIdx.x;
    int pair = t >> 5;
    int lane = t & 31;
    int b = pair >> 1, c = pair & 1;
    float acc = 0.f;
    for (int d = lane; d < DMODEL; d += 32) {
        float m = 0.f;
#pragma unroll
        for (int p = 0; p < 8; p++) m += part[(size_t)(b * 8 + p) * DMODEL + d];
        acc += m * Wc[c * DMODEL + d];
    }
#pragma unroll
    for (int off = 16; off; off >>= 1)
        acc += __shfl_xor_sync(0xffffffffu, acc, off);
    if (lane == 0) out[b * 2 + c] = acc * (1.f / SEQ) + bc[c];
}

// ---------------- launcher ----------------
static float* sym(const void* s) {
    void* p = nullptr;
    cudaGetSymbolAddress(&p, s);
    return (float*)p;
}

extern "C" void kernel_launch(void* const* d_in, const int* in_sizes, int n_in,
                              void* d_out, int out_size) {
    const int* C       = (const int*)d_in[0];
    const float* F     = (const float*)d_in[1];
    const float* W_fnn = (const float*)d_in[2];
    const float* b_fnn = (const float*)d_in[3];
    const float* in_w  = (const float*)d_in[4];
    const float* in_b  = (const float*)d_in[5];
    const float* out_w = (const float*)d_in[6];
    const float* out_b = (const float*)d_in[7];
    const float* ln1s  = (const float*)d_in[8];
    const float* ln1b  = (const float*)d_in[9];
    const float* W1    = (const float*)d_in[10];
    const float* b1    = (const float*)d_in[11];
    const float* W2    = (const float*)d_in[12];
    const float* b2    = (const float*)d_in[13];
    const float* ln2s  = (const float*)d_in[14];
    const float* ln2b  = (const float*)d_in[15];
    const float* ons   = (const float*)d_in[16];
    const float* onb   = (const float*)d_in[17];
    const float* Wc    = (const float*)d_in[18];
    const float* bc    = (const float*)d_in[19];
    float* out = (float*)d_out;

    float* pQ    = sym(g_Q);
    float* px    = sym(g_x);
    float* px2   = sym(g_x2);
    float* pq    = sym(g_q);
    float* pk    = sym(g_k);
    float* pv    = sym(g_v);
    float* po    = sym(g_o);
    float* pt    = sym(g_t);
    float* ph    = sym(g_h);
    float* py    = sym(g_y);
    float* ppart = sym(g_part);

    cudaFuncSetAttribute(flash_tf32, cudaFuncAttributeMaxDynamicSharedMemorySize, FA_SMEM);

    // 1) ROI embedding: Q = gelu(F @ W_fnn^T + b)
    {
        dim3 grid((DMODEL + BN - 1) / BN, (ROWS_Q + BM - 1) / BM);
        sgemm_nt<<<grid, 256>>>(F, W_fnn, b_fnn, pQ, ROWS_Q, DMODEL, DIN, 1,
                                nullptr, nullptr, nullptr);
    }
    // 2) gather + sum-pool -> tokens
    {
        dim3 grid(SEQ, BATCH);
        gather_pool<<<grid, DMODEL>>>(pQ, C, px);
    }
    // 3) qkv projection fused with head-split + q-scale
    {
        dim3 grid((3 * DMODEL + BN - 1) / BN, (ROWS_X + BM - 1) / BM);
        sgemm_nt<<<grid, 256>>>(px, in_w, in_b, nullptr, ROWS_X, 3 * DMODEL, DMODEL, 2,
                                pq, pk, pv);
    }
    // 4) attention (tf32 tensor-core flash)
    {
        dim3 grid((SEQ + 63) / 64, BATCH * NHEAD);
        flash_tf32<<<grid, 128, FA_SMEM>>>(pq, pk, pv, po);
    }
    // 5) out projection
    {
        dim3 grid((DMODEL + BN - 1) / BN, (ROWS_X + BM - 1) / BM);
        sgemm_nt<<<grid, 256>>>(po, out_w, out_b, pt, ROWS_X, DMODEL, DMODEL, 0,
                                nullptr, nullptr, nullptr);
    }
    // 6) x = LN(x + o)
    resid_ln<<<ROWS_X, DMODEL>>>(px, pt, ln1s, ln1b, px2);
    // 7) FFN1
    {
        dim3 grid((DFF + BN - 1) / BN, (ROWS_X + BM - 1) / BM);
        sgemm_nt<<<grid, 256>>>(px2, W1, b1, ph, ROWS_X, DFF, DMODEL, 1,
                                nullptr, nullptr, nullptr);
    }
    // 8) FFN2
    {
        dim3 grid((DMODEL + BN - 1) / BN, (ROWS_X + BM - 1) / BM);
        sgemm_nt<<<grid, 256>>>(ph, W2, b2, pt, ROWS_X, DMODEL, DFF, 0,
                                nullptr, nullptr, nullptr);
    }
    // 9) x = LN(x + t)
    resid_ln<<<ROWS_X, DMODEL>>>(px2, pt, ln2s, ln2b, px);
    // 10) output norm
    resid_ln<<<ROWS_X, DMODEL>>>(px, nullptr, ons, onb, py);
    // 11) mean over sequence
    {
        dim3 grid(BATCH, 8);
        mean_part<<<grid, DMODEL>>>(py, ppart);
    }
    // 12) classifier
    classifier<<<1, 256>>>(ppart, Wc, bc, out);
}

// round 4
// speedup vs baseline: 2.4610x; 1.2379x over previous
#include <cuda_runtime.h>
#include <cuda_bf16.h>
#include <math.h>

// ---------------- problem constants ----------------
#define BATCH 4
#define NROI 1632
#define DIN 1632
#define DMODEL 256
#define NHEAD 4
#define DHEAD 64
#define DFF 1024
#define SEQ 3375          // 15^3
#define ROWS_X (BATCH*SEQ)   // 13500
#define ROWS_Q (BATCH*NROI)  // 6528
#define LN_EPS 1e-5f

// ---------------- scratch (device globals; no allocation allowed) ----------------
__device__ float g_Q[ROWS_Q * DMODEL];
__device__ float g_x[ROWS_X * DMODEL];
__device__ float g_x2[ROWS_X * DMODEL];
__device__ float g_q[BATCH * NHEAD * SEQ * DHEAD];
__device__ float g_k[BATCH * NHEAD * SEQ * DHEAD];
__device__ float g_v[BATCH * NHEAD * SEQ * DHEAD];
__device__ float g_o[ROWS_X * DMODEL];
__device__ float g_t[ROWS_X * DMODEL];
__device__ float g_h[ROWS_X * DFF];
__device__ float g_y[ROWS_X * DMODEL];
__device__ float g_part[BATCH * 8 * DMODEL];

// ---------------- helpers ----------------
__device__ __forceinline__ float gelu_exact(float x) {
    return 0.5f * x * (1.0f + erff(x * 0.70710678118654752f));
}
__device__ __forceinline__ float to_tf32(float x) {
    float r;
    asm("cvt.rna.tf32.f32 %0, %1;" : "=f"(r) : "f"(x));
    return r;
}
__device__ __forceinline__ void mma_tf32(float* d, const unsigned* a,
                                         unsigned b0, unsigned b1) {
    asm volatile(
        "mma.sync.aligned.m16n8k8.row.col.f32.tf32.tf32.f32 "
        "{%0,%1,%2,%3}, {%4,%5,%6,%7}, {%8,%9}, {%0,%1,%2,%3};\n"
        : "+f"(d[0]), "+f"(d[1]), "+f"(d[2]), "+f"(d[3])
        : "r"(a[0]), "r"(a[1]), "r"(a[2]), "r"(a[3]), "r"(b0), "r"(b1));
}

// ---------------- tensor-core 3xTF32 GEMM ----------------
// C[m,n] = act(sum_k A[m,k]*B[n,k] + bias[n])
// CTA tile 128x64, BK=16, 256 threads = 8 warps (4m x 2n), warp tile 32x32.
// act: 0 = none, 1 = gelu, 2 = qkv-split epilogue (writes qp/kp/vp).
// Requires K % 16 == 0, N % 64 == 0.
#define GBM 128
#define GBN 64
#define GBK 16
#define GPAD 20

__global__ void __launch_bounds__(256, 2)
gemm3t(const float* __restrict__ A, const float* __restrict__ B,
       const float* __restrict__ bias, float* __restrict__ C,
       int M, int N, int K, int act,
       float* __restrict__ qp, float* __restrict__ kp, float* __restrict__ vp) {
    __shared__ float Ah[GBM * GPAD], Al[GBM * GPAD];
    __shared__ float Bh[GBN * GPAD], Bl[GBN * GPAD];

    const int bm = blockIdx.y * GBM;
    const int bn = blockIdx.x * GBN;
    const int tid = threadIdx.x;
    const int warp = tid >> 5, lane = tid & 31;
    const int g = lane >> 2, t = lane & 3;
    const int wm = warp >> 1, wn = warp & 1;

    // A staging: thread -> row am, k-half ac (two float4 each covering 8 k)
    const int am = tid >> 1, ac = tid & 1;
    // B staging: thread -> row bnr, k-quarter bq (one float4)
    const int bnr = tid >> 2, bq = tid & 3;

    float acc[2][4][4];
#pragma unroll
    for (int mi = 0; mi < 2; mi++)
#pragma unroll
        for (int ni = 0; ni < 4; ni++)
#pragma unroll
            for (int v = 0; v < 4; v++) acc[mi][ni][v] = 0.f;

    const int arow = bm + am;
    const int brow = bn + bnr;

    for (int k0 = 0; k0 < K; k0 += GBK) {
        // ---- stage A (hi/lo) ----
        float4 a0 = make_float4(0.f, 0.f, 0.f, 0.f);
        float4 a1 = make_float4(0.f, 0.f, 0.f, 0.f);
        if (arow < M) {
            a0 = *reinterpret_cast<const float4*>(&A[(size_t)arow * K + k0 + 8 * ac]);
            a1 = *reinterpret_cast<const float4*>(&A[(size_t)arow * K + k0 + 8 * ac + 4]);
        }
        {
            float4 h, l;
            h.x = to_tf32(a0.x); l.x = to_tf32(a0.x - h.x);
            h.y = to_tf32(a0.y); l.y = to_tf32(a0.y - h.y);
            h.z = to_tf32(a0.z); l.z = to_tf32(a0.z - h.z);
            h.w = to_tf32(a0.w); l.w = to_tf32(a0.w - h.w);
            *reinterpret_cast<float4*>(&Ah[am * GPAD + 8 * ac]) = h;
            *reinterpret_cast<float4*>(&Al[am * GPAD + 8 * ac]) = l;
            h.x = to_tf32(a1.x); l.x = to_tf32(a1.x - h.x);
            h.y = to_tf32(a1.y); l.y = to_tf32(a1.y - h.y);
            h.z = to_tf32(a1.z); l.z = to_tf32(a1.z - h.z);
            h.w = to_tf32(a1.w); l.w = to_tf32(a1.w - h.w);
            *reinterpret_cast<float4*>(&Ah[am * GPAD + 8 * ac + 4]) = h;
            *reinterpret_cast<float4*>(&Al[am * GPAD + 8 * ac + 4]) = l;
        }
        // ---- stage B (hi/lo) ----
        {
            float4 b4 = *reinterpret_cast<const float4*>(&B[(size_t)brow * K + k0 + 4 * bq]);
            float4 h, l;
            h.x = to_tf32(b4.x); l.x = to_tf32(b4.x - h.x);
            h.y = to_tf32(b4.y); l.y = to_tf32(b4.y - h.y);
            h.z = to_tf32(b4.z); l.z = to_tf32(b4.z - h.z);
            h.w = to_tf32(b4.w); l.w = to_tf32(b4.w - h.w);
            *reinterpret_cast<float4*>(&Bh[bnr * GPAD + 4 * bq]) = h;
            *reinterpret_cast<float4*>(&Bl[bnr * GPAD + 4 * bq]) = l;
        }
        __syncthreads();

#pragma unroll
        for (int kc = 0; kc < 2; kc++) {
            unsigned ah[2][4], al[2][4];
#pragma unroll
            for (int mi = 0; mi < 2; mi++) {
                int m0 = wm * 32 + mi * 16;
                int kk = kc * 8 + t;
                ah[mi][0] = __float_as_uint(Ah[(m0 + g) * GPAD + kk]);
                ah[mi][1] = __float_as_uint(Ah[(m0 + g + 8) * GPAD + kk]);
                ah[mi][2] = __float_as_uint(Ah[(m0 + g) * GPAD + kk + 4]);
                ah[mi][3] = __float_as_uint(Ah[(m0 + g + 8) * GPAD + kk + 4]);
                al[mi][0] = __float_as_uint(Al[(m0 + g) * GPAD + kk]);
                al[mi][1] = __float_as_uint(Al[(m0 + g + 8) * GPAD + kk]);
                al[mi][2] = __float_as_uint(Al[(m0 + g) * GPAD + kk + 4]);
                al[mi][3] = __float_as_uint(Al[(m0 + g + 8) * GPAD + kk + 4]);
            }
            unsigned bh[4][2], bl[4][2];
#pragma unroll
            for (int ni = 0; ni < 4; ni++) {
                int n0 = wn * 32 + ni * 8;
                int kk = kc * 8 + t;
                bh[ni][0] = __float_as_uint(Bh[(n0 + g) * GPAD + kk]);
                bh[ni][1] = __float_as_uint(Bh[(n0 + g) * GPAD + kk + 4]);
                bl[ni][0] = __float_as_uint(Bl[(n0 + g) * GPAD + kk]);
                bl[ni][1] = __float_as_uint(Bl[(n0 + g) * GPAD + kk + 4]);
            }
#pragma unroll
            for (int mi = 0; mi < 2; mi++)
#pragma unroll
                for (int ni = 0; ni < 4; ni++) {
                    mma_tf32(acc[mi][ni], ah[mi], bh[ni][0], bh[ni][1]);
                    mma_tf32(acc[mi][ni], al[mi], bh[ni][0], bh[ni][1]);
                    mma_tf32(acc[mi][ni], ah[mi], bl[ni][0], bl[ni][1]);
                }
        }
        __syncthreads();
    }

    // ---- epilogue ----
    if (act != 2) {
#pragma unroll
        for (int mi = 0; mi < 2; mi++) {
            int m0 = bm + wm * 32 + mi * 16;
            int row0 = m0 + g;
            int row1 = m0 + g + 8;
#pragma unroll
            for (int ni = 0; ni < 4; ni++) {
                int col = bn + wn * 32 + ni * 8 + 2 * t;
                float b0 = bias[col], b1 = bias[col + 1];
                if (row0 < M) {
                    float v0 = acc[mi][ni][0] + b0;
                    float v1 = acc[mi][ni][1] + b1;
                    if (act == 1) { v0 = gelu_exact(v0); v1 = gelu_exact(v1); }
                    *reinterpret_cast<float2*>(&C[(size_t)row0 * N + col]) = make_float2(v0, v1);
                }
                if (row1 < M) {
                    float v2 = acc[mi][ni][2] + b0;
                    float v3 = acc[mi][ni][3] + b1;
                    if (act == 1) { v2 = gelu_exact(v2); v3 = gelu_exact(v3); }
                    *reinterpret_cast<float2*>(&C[(size_t)row1 * N + col]) = make_float2(v2, v3);
                }
            }
        }
    } else {
        // qkv-split epilogue: N=768; cols [0,256)=q (x0.125), [256,512)=k, [512,768)=v.
#pragma unroll
        for (int mi = 0; mi < 2; mi++) {
            int m0 = bm + wm * 32 + mi * 16;
#pragma unroll
            for (int ni = 0; ni < 4; ni++) {
                int col = bn + wn * 32 + ni * 8 + 2 * t;
                int sec = col >> 8;
                int d = col & 255;
                int h = d >> 6;
                int dh = d & 63;
                float* dst = (sec == 0) ? qp : (sec == 1) ? kp : vp;
                float scale = (sec == 0) ? 0.125f : 1.f;
                float b0 = bias[col], b1 = bias[col + 1];
                int row0 = m0 + g;
                int row1 = m0 + g + 8;
                if (row0 < M) {
                    int b = row0 / SEQ, s = row0 - b * SEQ;
                    size_t base = ((size_t)(b * NHEAD + h) * SEQ + s) * DHEAD + dh;
                    *reinterpret_cast<float2*>(&dst[base]) =
                        make_float2((acc[mi][ni][0] + b0) * scale, (acc[mi][ni][1] + b1) * scale);
                }
                if (row1 < M) {
                    int b = row1 / SEQ, s = row1 - b * SEQ;
                    size_t base = ((size_t)(b * NHEAD + h) * SEQ + s) * DHEAD + dh;
                    *reinterpret_cast<float2*>(&dst[base]) =
                        make_float2((acc[mi][ni][2] + b0) * scale, (acc[mi][ni][3] + b1) * scale);
                }
            }
        }
    }
}

// ---------------- gather + sum-pool ----------------
__global__ void gather_pool(const float* __restrict__ Q, const int* __restrict__ C,
                            float* __restrict__ out) {
    int o = blockIdx.x;
    int b = blockIdx.y;
    int d = threadIdx.x;
    int oz = o % 15;
    int oy = (o / 15) % 15;
    int ox = o / 225;
    const float* Qb = Q + (size_t)b * NROI * DMODEL;
    const int* Cb = C + (size_t)b * 32 * 32 * 32;
    float acc = 0.f;
#pragma unroll
    for (int dx = 0; dx < 3; dx++) {
        int x = 2 * ox + dx;
#pragma unroll
        for (int dy = 0; dy < 3; dy++) {
            int y = 2 * oy + dy;
#pragma unroll
            for (int dz = 0; dz < 3; dz++) {
                int z = 2 * oz + dz;
                int idx = Cb[(x * 32 + y) * 32 + z];
                acc += Qb[(size_t)idx * DMODEL + d];
            }
        }
    }
    out[((size_t)b * SEQ + o) * DMODEL + d] = acc;
}

// ---------------- flash attention, tf32 mma.sync ----------------
#define KPAD 68
#define VPAD 72
#define FA_SMEM ((64*68 + 64*72 + 64*68) * 4)

__global__ void __launch_bounds__(128, 3)
flash_tf32(const float* __restrict__ Qm, const float* __restrict__ Km,
           const float* __restrict__ Vm, float* __restrict__ O) {
    extern __shared__ float sm[];
    float* Ks = sm;
    float* Vs = sm + 64 * KPAD;
    float* Ps = sm + 64 * KPAD + 64 * VPAD;

    const int bh = blockIdx.y;
    const int q0 = blockIdx.x * 64;
    const int tid = threadIdx.x;
    const int warp = tid >> 5;
    const int lane = tid & 31;
    const int g = lane >> 2;
    const int t = lane & 3;

    const float* qb = Qm + (size_t)bh * SEQ * DHEAD;
    const float* kb = Km + (size_t)bh * SEQ * DHEAD;
    const float* vb = Vm + (size_t)bh * SEQ * DHEAD;

#pragma unroll
    for (int it = 0; it < 8; it++) {
        int idx = tid + it * 128;
        int row = idx >> 4;
        int c4 = (idx & 15) << 2;
        float4 v = make_float4(0.f, 0.f, 0.f, 0.f);
        if (q0 + row < SEQ) v = *reinterpret_cast<const float4*>(&qb[(size_t)(q0 + row) * 64 + c4]);
        v.x = to_tf32(v.x); v.y = to_tf32(v.y); v.z = to_tf32(v.z); v.w = to_tf32(v.w);
        *reinterpret_cast<float4*>(&Ps[row * KPAD + c4]) = v;
    }
    __syncthreads();

    const int pr = 16 * warp;
    unsigned qa[8][4];
#pragma unroll
    for (int kc = 0; kc < 8; kc++) {
        qa[kc][0] = __float_as_uint(Ps[(pr + g) * KPAD + kc * 8 + t]);
        qa[kc][1] = __float_as_uint(Ps[(pr + g + 8) * KPAD + kc * 8 + t]);
        qa[kc][2] = __float_as_uint(Ps[(pr + g) * KPAD + kc * 8 + t + 4]);
        qa[kc][3] = __float_as_uint(Ps[(pr + g + 8) * KPAD + kc * 8 + t + 4]);
    }

    float oc[8][4];
    float mi[2] = {-1e30f, -1e30f};
    float li[2] = {0.f, 0.f};
#pragma unroll
    for (int n = 0; n < 8; n++)
#pragma unroll
        for (int v = 0; v < 4; v++) oc[n][v] = 0.f;

    const int nkt = (SEQ + 63) / 64;
    for (int kt = 0; kt < nkt; kt++) {
        int k0 = kt * 64;
#pragma unroll
        for (int it = 0; it < 8; it++) {
            int idx = tid + it * 128;
            int row = idx >> 4;
            int c4 = (idx & 15) << 2;
            float4 kv = make_float4(0.f, 0.f, 0.f, 0.f);
            float4 vv = make_float4(0.f, 0.f, 0.f, 0.f);
            if (k0 + row < SEQ) {
                kv = *reinterpret_cast<const float4*>(&kb[(size_t)(k0 + row) * 64 + c4]);
                vv = *reinterpret_cast<const float4*>(&vb[(size_t)(k0 + row) * 64 + c4]);
            }
            kv.x = to_tf32(kv.x); kv.y = to_tf32(kv.y); kv.z = to_tf32(kv.z); kv.w = to_tf32(kv.w);
            vv.x = to_tf32(vv.x); vv.y = to_tf32(vv.y); vv.z = to_tf32(vv.z); vv.w = to_tf32(vv.w);
            *reinterpret_cast<float4*>(&Ks[row * KPAD + c4]) = kv;
            *reinterpret_cast<float4*>(&Vs[row * VPAD + c4]) = vv;
        }
        __syncthreads();

        float sf[8][4];
#pragma unroll
        for (int n = 0; n < 8; n++) {
            sf[n][0] = sf[n][1] = sf[n][2] = sf[n][3] = 0.f;
#pragma unroll
            for (int kc = 0; kc < 8; kc++) {
                unsigned b0 = __float_as_uint(Ks[(n * 8 + g) * KPAD + kc * 8 + t]);
                unsigned b1 = __float_as_uint(Ks[(n * 8 + g) * KPAD + kc * 8 + t + 4]);
                mma_tf32(sf[n], qa[kc], b0, b1);
            }
        }

        if (k0 + 64 > SEQ) {
            int lim = SEQ - k0;
#pragma unroll
            for (int n = 0; n < 8; n++) {
                int c0 = n * 8 + 2 * t;
                if (c0 >= lim) { sf[n][0] = -1e30f; sf[n][2] = -1e30f; }
                if (c0 + 1 >= lim) { sf[n][1] = -1e30f; sf[n][3] = -1e30f; }
            }
        }

        float tm0 = -1e30f, tm1 = -1e30f;
#pragma unroll
        for (int n = 0; n < 8; n++) {
            tm0 = fmaxf(tm0, fmaxf(sf[n][0], sf[n][1]));
            tm1 = fmaxf(tm1, fmaxf(sf[n][2], sf[n][3]));
        }
        tm0 = fmaxf(tm0, __shfl_xor_sync(0xffffffffu, tm0, 1));
        tm0 = fmaxf(tm0, __shfl_xor_sync(0xffffffffu, tm0, 2));
        tm1 = fmaxf(tm1, __shfl_xor_sync(0xffffffffu, tm1, 1));
        tm1 = fmaxf(tm1, __shfl_xor_sync(0xffffffffu, tm1, 2));
        float mn0 = fmaxf(mi[0], tm0);
        float mn1 = fmaxf(mi[1], tm1);
        float a0 = __expf(mi[0] - mn0);
        float a1 = __expf(mi[1] - mn1);
        float rs0 = 0.f, rs1 = 0.f;
#pragma unroll
        for (int n = 0; n < 8; n++) {
            float p0 = __expf(sf[n][0] - mn0);
            float p1 = __expf(sf[n][1] - mn0);
            float p2 = __expf(sf[n][2] - mn1);
            float p3 = __expf(sf[n][3] - mn1);
            rs0 += p0 + p1;
            rs1 += p2 + p3;
            float2 lo = make_float2(to_tf32(p0), to_tf32(p1));
            float2 hi = make_float2(to_tf32(p2), to_tf32(p3));
            *reinterpret_cast<float2*>(&Ps[(pr + g) * KPAD + n * 8 + 2 * t]) = lo;
            *reinterpret_cast<float2*>(&Ps[(pr + g + 8) * KPAD + n * 8 + 2 * t]) = hi;
        }
        rs0 += __shfl_xor_sync(0xffffffffu, rs0, 1);
        rs0 += __shfl_xor_sync(0xffffffffu, rs0, 2);
        rs1 += __shfl_xor_sync(0xffffffffu, rs1, 1);
        rs1 += __shfl_xor_sync(0xffffffffu, rs1, 2);
        li[0] = li[0] * a0 + rs0;
        li[1] = li[1] * a1 + rs1;
        mi[0] = mn0;
        mi[1] = mn1;
#pragma unroll
        for (int n = 0; n < 8; n++) {
            oc[n][0] *= a0; oc[n][1] *= a0;
            oc[n][2] *= a1; oc[n][3] *= a1;
        }
        __syncwarp();

#pragma unroll
        for (int kc = 0; kc < 8; kc++) {
            unsigned pa[4];
            pa[0] = __float_as_uint(Ps[(pr + g) * KPAD + kc * 8 + t]);
            pa[1] = __float_as_uint(Ps[(pr + g + 8) * KPAD + kc * 8 + t]);
            pa[2] = __float_as_uint(Ps[(pr + g) * KPAD + kc * 8 + t + 4]);
            pa[3] = __float_as_uint(Ps[(pr + g + 8) * KPAD + kc * 8 + t + 4]);
#pragma unroll
            for (int n = 0; n < 8; n++) {
                unsigned b0 = __float_as_uint(Vs[(kc * 8 + t) * VPAD + n * 8 + g]);
                unsigned b1 = __float_as_uint(Vs[(kc * 8 + t + 4) * VPAD + n * 8 + g]);
                mma_tf32(oc[n], pa, b0, b1);
            }
        }
        __syncthreads();
    }

    const int b = bh >> 2;
    const int h = bh & 3;
    float inv0 = 1.f / li[0];
    float inv1 = 1.f / li[1];
    int qr0 = q0 + pr + g;
    int qr1 = qr0 + 8;
#pragma unroll
    for (int n = 0; n < 8; n++) {
        int d = h * 64 + n * 8 + 2 * t;
        if (qr0 < SEQ) {
            float2 o2 = make_float2(oc[n][0] * inv0, oc[n][1] * inv0);
            *reinterpret_cast<float2*>(&O[((size_t)(b * SEQ + qr0)) * DMODEL + d]) = o2;
        }
        if (qr1 < SEQ) {
            float2 o2 = make_float2(oc[n][2] * inv1, oc[n][3] * inv1);
            *reinterpret_cast<float2*>(&O[((size_t)(b * SEQ + qr1)) * DMODEL + d]) = o2;
        }
    }
}

// ---------------- residual + LayerNorm (R may be null) ----------------
__global__ void resid_ln(const float* __restrict__ X, const float* __restrict__ R,
                         const float* __restrict__ sc, const float* __restrict__ bi,
                         float* __restrict__ out) {
    int row = blockIdx.x;
    int d = threadIdx.x;
    size_t base = (size_t)row * DMODEL;
    float v = X[base + d];
    if (R) v += R[base + d];

    float s1 = v, s2 = v * v;
#pragma unroll
    for (int off = 16; off; off >>= 1) {
        s1 += __shfl_xor_sync(0xffffffffu, s1, off);
        s2 += __shfl_xor_sync(0xffffffffu, s2, off);
    }
    __shared__ float r1[8], r2[8];
    int warp = d >> 5, lane = d & 31;
    if (lane == 0) { r1[warp] = s1; r2[warp] = s2; }
    __syncthreads();
    if (d < 8) {
        float a = r1[d], b2 = r2[d];
#pragma unroll
        for (int off = 4; off; off >>= 1) {
            a += __shfl_xor_sync(0xffu, a, off);
            b2 += __shfl_xor_sync(0xffu, b2, off);
        }
        if (d == 0) { r1[0] = a; r2[0] = b2; }
    }
    __syncthreads();
    float mean = r1[0] * (1.f / DMODEL);
    float var = r2[0] * (1.f / DMODEL) - mean * mean;
    out[base + d] = (v - mean) * rsqrtf(var + LN_EPS) * sc[d] + bi[d];
}

// ---------------- partial mean over sequence ----------------
__global__ void mean_part(const float* __restrict__ Y, float* __restrict__ part) {
    int b = blockIdx.x;
    int c = blockIdx.y;
    int d = threadIdx.x;
    const int CH = (SEQ + 7) / 8;
    int s0 = c * CH;
    int s1 = min(SEQ, s0 + CH);
    float acc = 0.f;
    for (int s = s0; s < s1; s++)
        acc += Y[((size_t)b * SEQ + s) * DMODEL + d];
    part[(size_t)(b * 8 + c) * DMODEL + d] = acc;
}

// ---------------- classifier ----------------
__global__ void classifier(const float* __restrict__ part, const float* __restrict__ Wc,
                           const float* __restrict__ bc, float* __restrict__ out) {
    int t = threadIdx.x;
    int pair = t >> 5;
    int lane = t & 31;
    int b = pair >> 1, c = pair & 1;
    float acc = 0.f;
    for (int d = lane; d < DMODEL; d += 32) {
        float m = 0.f;
#pragma unroll
        for (int p = 0; p < 8; p++) m += part[(size_t)(b * 8 + p) * DMODEL + d];
        acc += m * Wc[c * DMODEL + d];
    }
#pragma unroll
    for (int off = 16; off; off >>= 1)
        acc += __shfl_xor_sync(0xffffffffu, acc, off);
    if (lane == 0) out[b * 2 + c] = acc * (1.f / SEQ) + bc[c];
}

// ---------------- launcher ----------------
static float* sym(const void* s) {
    void* p = nullptr;
    cudaGetSymbolAddress(&p, s);
    return (float*)p;
}

extern "C" void kernel_launch(void* const* d_in, const int* in_sizes, int n_in,
                              void* d_out, int out_size) {
    const int* C       = (const int*)d_in[0];
    const float* F     = (const float*)d_in[1];
    const float* W_fnn = (const float*)d_in[2];
    const float* b_fnn = (const float*)d_in[3];
    const float* in_w  = (const float*)d_in[4];
    const float* in_b  = (const float*)d_in[5];
    const float* out_w = (const float*)d_in[6];
    const float* out_b = (const float*)d_in[7];
    const float* ln1s  = (const float*)d_in[8];
    const float* ln1b  = (const float*)d_in[9];
    const float* W1    = (const float*)d_in[10];
    const float* b1    = (const float*)d_in[11];
    const float* W2    = (const float*)d_in[12];
    const float* b2    = (const float*)d_in[13];
    const float* ln2s  = (const float*)d_in[14];
    const float* ln2b  = (const float*)d_in[15];
    const float* ons   = (const float*)d_in[16];
    const float* onb   = (const float*)d_in[17];
    const float* Wc    = (const float*)d_in[18];
    const float* bc    = (const float*)d_in[19];
    float* out = (float*)d_out;

    float* pQ    = sym(g_Q);
    float* px    = sym(g_x);
    float* px2   = sym(g_x2);
    float* pq    = sym(g_q);
    float* pk    = sym(g_k);
    float* pv    = sym(g_v);
    float* po    = sym(g_o);
    float* pt    = sym(g_t);
    float* ph    = sym(g_h);
    float* py    = sym(g_y);
    float* ppart = sym(g_part);

    cudaFuncSetAttribute(flash_tf32, cudaFuncAttributeMaxDynamicSharedMemorySize, FA_SMEM);

    // 1) ROI embedding: Q = gelu(F @ W_fnn^T + b)   (6528 x 256, K=1632)
    {
        dim3 grid(DMODEL / GBN, (ROWS_Q + GBM - 1) / GBM);
        gemm3t<<<grid, 256>>>(F, W_fnn, b_fnn, pQ, ROWS_Q, DMODEL, DIN, 1,
                              nullptr, nullptr, nullptr);
    }
    // 2) gather + sum-pool -> tokens
    {
        dim3 grid(SEQ, BATCH);
        gather_pool<<<grid, DMODEL>>>(pQ, C, px);
    }
    // 3) qkv projection fused with head-split + q-scale (13500 x 768, K=256)
    {
        dim3 grid((3 * DMODEL) / GBN, (ROWS_X + GBM - 1) / GBM);
        gemm3t<<<grid, 256>>>(px, in_w, in_b, nullptr, ROWS_X, 3 * DMODEL, DMODEL, 2,
                              pq, pk, pv);
    }
    // 4) attention (tf32 tensor-core flash)
    {
        dim3 grid((SEQ + 63) / 64, BATCH * NHEAD);
        flash_tf32<<<grid, 128, FA_SMEM>>>(pq, pk, pv, po);
    }
    // 5) out projection (13500 x 256, K=256)
    {
        dim3 grid(DMODEL / GBN, (ROWS_X + GBM - 1) / GBM);
        gemm3t<<<grid, 256>>>(po, out_w, out_b, pt, ROWS_X, DMODEL, DMODEL, 0,
                              nullptr, nullptr, nullptr);
    }
    // 6) x = LN(x + o)
    resid_ln<<<ROWS_X, DMODEL>>>(px, pt, ln1s, ln1b, px2);
    // 7) FFN1: h = gelu(x @ W1^T + b1)   (13500 x 1024, K=256)
    {
        dim3 grid(DFF / GBN, (ROWS_X + GBM - 1) / GBM);
        gemm3t<<<grid, 256>>>(px2, W1, b1, ph, ROWS_X, DFF, DMODEL, 1,
                              nullptr, nullptr, nullptr);
    }
    // 8) FFN2: t = h @ W2^T + b2   (13500 x 256, K=1024)
    {
        dim3 grid(DMODEL / GBN, (ROWS_X + GBM - 1) / GBM);
        gemm3t<<<grid, 256>>>(ph, W2, b2, pt, ROWS_X, DMODEL, DFF, 0,
                              nullptr, nullptr, nullptr);
    }
    // 9) x = LN(x + t)
    resid_ln<<<ROWS_X, DMODEL>>>(px2, pt, ln2s, ln2b, px);
    // 10) output norm
    resid_ln<<<ROWS_X, DMODEL>>>(px, nullptr, ons, onb, py);
    // 11) mean over sequence
    {
        dim3 grid(BATCH, 8);
        mean_part<<<grid, DMODEL>>>(py, ppart);
    }
    // 12) classifier
    classifier<<<1, 256>>>(ppart, Wc, bc, out);
}

// round 5
// speedup vs baseline: 2.5538x; 1.0377x over previous
#include <cuda_runtime.h>
#include <cuda_bf16.h>
#include <math.h>

// ---------------- problem constants ----------------
#define BATCH 4
#define NROI 1632
#define DIN 1632
#define DMODEL 256
#define NHEAD 4
#define DHEAD 64
#define DFF 1024
#define SEQ 3375          // 15^3
#define ROWS_X (BATCH*SEQ)   // 13500
#define ROWS_Q (BATCH*NROI)  // 6528
#define LN_EPS 1e-5f

// ---------------- scratch (device globals; no allocation allowed) ----------------
__device__ float g_Q[ROWS_Q * DMODEL];
__device__ float g_x[ROWS_X * DMODEL];
__device__ float g_x2[ROWS_X * DMODEL];
__device__ float g_q[BATCH * NHEAD * SEQ * DHEAD];
__device__ float g_k[BATCH * NHEAD * SEQ * DHEAD];
__device__ float g_v[BATCH * NHEAD * SEQ * DHEAD];
__device__ float g_o[ROWS_X * DMODEL];
__device__ float g_t[ROWS_X * DMODEL];
__device__ float g_h[ROWS_X * DFF];
__device__ float g_y[ROWS_X * DMODEL];
__device__ float g_part[BATCH * 8 * DMODEL];

// ---------------- helpers ----------------
__device__ __forceinline__ float gelu_exact(float x) {
    return 0.5f * x * (1.0f + erff(x * 0.70710678118654752f));
}
__device__ __forceinline__ float to_tf32(float x) {
    float r;
    asm("cvt.rna.tf32.f32 %0, %1;" : "=f"(r) : "f"(x));
    return r;
}
__device__ __forceinline__ void mma_tf32(float* d, const unsigned* a,
                                         unsigned b0, unsigned b1) {
    asm volatile(
        "mma.sync.aligned.m16n8k8.row.col.f32.tf32.tf32.f32 "
        "{%0,%1,%2,%3}, {%4,%5,%6,%7}, {%8,%9}, {%0,%1,%2,%3};\n"
        : "+f"(d[0]), "+f"(d[1]), "+f"(d[2]), "+f"(d[3])
        : "r"(a[0]), "r"(a[1]), "r"(a[2]), "r"(a[3]), "r"(b0), "r"(b1));
}

// ---------------- tensor-core 3xTF32 GEMM, double-buffered ----------------
// C[m,n] = act(sum_k A[m,k]*B[n,k] + bias[n])
// CTA tile 128x64, BK=16, 256 threads = 8 warps (4m x 2n), warp tile 32x32.
// act: 0 = none, 1 = gelu, 2 = qkv-split epilogue (writes qp/kp/vp).
// Requires K % 16 == 0, N % 64 == 0.
#define GBM 128
#define GBN 64
#define GBK 16
#define GPAD 20
// per-buffer float counts
#define G_AH (GBM * GPAD)          // 2560
#define G_B  (GBN * GPAD)          // 1280
#define G_BUF (2 * G_AH + 2 * G_B) // 7680 floats = 30720 B
#define G_SMEM (2 * G_BUF * 4)     // 61440 B

__global__ void __launch_bounds__(256, 2)
gemm3t(const float* __restrict__ A, const float* __restrict__ B,
       const float* __restrict__ bias, float* __restrict__ C,
       int M, int N, int K, int act,
       float* __restrict__ qp, float* __restrict__ kp, float* __restrict__ vp) {
    extern __shared__ float smg[];

    const int bm = blockIdx.y * GBM;
    const int bn = blockIdx.x * GBN;
    const int tid = threadIdx.x;
    const int warp = tid >> 5, lane = tid & 31;
    const int g = lane >> 2, t = lane & 3;
    const int wm = warp >> 1, wn = warp & 1;

    // A staging: thread -> row am, k-half ac (two float4 covering 8 k)
    const int am = tid >> 1, ac = tid & 1;
    // B staging: thread -> row bnr, k-quarter bq (one float4)
    const int bnr = tid >> 2, bq = tid & 3;
    const int arow = bm + am;
    const int brow = bn + bnr;

    float acc[2][4][4];
#pragma unroll
    for (int mi = 0; mi < 2; mi++)
#pragma unroll
        for (int ni = 0; ni < 4; ni++)
#pragma unroll
            for (int v = 0; v < 4; v++) acc[mi][ni][v] = 0.f;

    const int niter = K / GBK;

    float4 ra0, ra1, rb;
    // ---- prologue: load tile 0 ----
    {
        ra0 = make_float4(0.f, 0.f, 0.f, 0.f);
        ra1 = ra0;
        if (arow < M) {
            ra0 = *reinterpret_cast<const float4*>(&A[(size_t)arow * K + 8 * ac]);
            ra1 = *reinterpret_cast<const float4*>(&A[(size_t)arow * K + 8 * ac + 4]);
        }
        rb = *reinterpret_cast<const float4*>(&B[(size_t)brow * K + 4 * bq]);
        float* Ah = smg;
        float* Al = Ah + G_AH;
        float* Bh = Al + G_AH;
        float* Bl = Bh + G_B;
        float4 h, l;
        h.x = to_tf32(ra0.x); l.x = to_tf32(ra0.x - h.x);
        h.y = to_tf32(ra0.y); l.y = to_tf32(ra0.y - h.y);
        h.z = to_tf32(ra0.z); l.z = to_tf32(ra0.z - h.z);
        h.w = to_tf32(ra0.w); l.w = to_tf32(ra0.w - h.w);
        *reinterpret_cast<float4*>(&Ah[am * GPAD + 8 * ac]) = h;
        *reinterpret_cast<float4*>(&Al[am * GPAD + 8 * ac]) = l;
        h.x = to_tf32(ra1.x); l.x = to_tf32(ra1.x - h.x);
        h.y = to_tf32(ra1.y); l.y = to_tf32(ra1.y - h.y);
        h.z = to_tf32(ra1.z); l.z = to_tf32(ra1.z - h.z);
        h.w = to_tf32(ra1.w); l.w = to_tf32(ra1.w - h.w);
        *reinterpret_cast<float4*>(&Ah[am * GPAD + 8 * ac + 4]) = h;
        *reinterpret_cast<float4*>(&Al[am * GPAD + 8 * ac + 4]) = l;
        h.x = to_tf32(rb.x); l.x = to_tf32(rb.x - h.x);
        h.y = to_tf32(rb.y); l.y = to_tf32(rb.y - h.y);
        h.z = to_tf32(rb.z); l.z = to_tf32(rb.z - h.z);
        h.w = to_tf32(rb.w); l.w = to_tf32(rb.w - h.w);
        *reinterpret_cast<float4*>(&Bh[bnr * GPAD + 4 * bq]) = h;
        *reinterpret_cast<float4*>(&Bl[bnr * GPAD + 4 * bq]) = l;
    }
    __syncthreads();

    for (int it = 0; it < niter; it++) {
        const int buf = it & 1;
        const bool have_next = (it + 1 < niter);
        // ---- prefetch next tile into registers (overlaps with compute) ----
        if (have_next) {
            int k0 = (it + 1) * GBK;
            ra0 = make_float4(0.f, 0.f, 0.f, 0.f);
            ra1 = ra0;
            if (arow < M) {
                ra0 = *reinterpret_cast<const float4*>(&A[(size_t)arow * K + k0 + 8 * ac]);
                ra1 = *reinterpret_cast<const float4*>(&A[(size_t)arow * K + k0 + 8 * ac + 4]);
            }
            rb = *reinterpret_cast<const float4*>(&B[(size_t)brow * K + k0 + 4 * bq]);
        }

        // ---- compute on current buffer ----
        {
            const float* Ah = smg + buf * G_BUF;
            const float* Al = Ah + G_AH;
            const float* Bh = Al + G_AH;
            const float* Bl = Bh + G_B;
#pragma unroll
            for (int kc = 0; kc < 2; kc++) {
                unsigned ah[2][4], al[2][4];
#pragma unroll
                for (int mi = 0; mi < 2; mi++) {
                    int m0 = wm * 32 + mi * 16;
                    int kk = kc * 8 + t;
                    ah[mi][0] = __float_as_uint(Ah[(m0 + g) * GPAD + kk]);
                    ah[mi][1] = __float_as_uint(Ah[(m0 + g + 8) * GPAD + kk]);
                    ah[mi][2] = __float_as_uint(Ah[(m0 + g) * GPAD + kk + 4]);
                    ah[mi][3] = __float_as_uint(Ah[(m0 + g + 8) * GPAD + kk + 4]);
                    al[mi][0] = __float_as_uint(Al[(m0 + g) * GPAD + kk]);
                    al[mi][1] = __float_as_uint(Al[(m0 + g + 8) * GPAD + kk]);
                    al[mi][2] = __float_as_uint(Al[(m0 + g) * GPAD + kk + 4]);
                    al[mi][3] = __float_as_uint(Al[(m0 + g + 8) * GPAD + kk + 4]);
                }
                unsigned bh[4][2], bl[4][2];
#pragma unroll
                for (int ni = 0; ni < 4; ni++) {
                    int n0 = wn * 32 + ni * 8;
                    int kk = kc * 8 + t;
                    bh[ni][0] = __float_as_uint(Bh[(n0 + g) * GPAD + kk]);
                    bh[ni][1] = __float_as_uint(Bh[(n0 + g) * GPAD + kk + 4]);
                    bl[ni][0] = __float_as_uint(Bl[(n0 + g) * GPAD + kk]);
                    bl[ni][1] = __float_as_uint(Bl[(n0 + g) * GPAD + kk + 4]);
                }
#pragma unroll
                for (int mi = 0; mi < 2; mi++)
#pragma unroll
                    for (int ni = 0; ni < 4; ni++) {
                        mma_tf32(acc[mi][ni], ah[mi], bh[ni][0], bh[ni][1]);
                        mma_tf32(acc[mi][ni], al[mi], bh[ni][0], bh[ni][1]);
                        mma_tf32(acc[mi][ni], ah[mi], bl[ni][0], bl[ni][1]);
                    }
            }
        }

        // ---- store prefetched tile into alternate buffer ----
        if (have_next) {
            float* Ah = smg + (buf ^ 1) * G_BUF;
            float* Al = Ah + G_AH;
            float* Bh = Al + G_AH;
            float* Bl = Bh + G_B;
            float4 h, l;
            h.x = to_tf32(ra0.x); l.x = to_tf32(ra0.x - h.x);
            h.y = to_tf32(ra0.y); l.y = to_tf32(ra0.y - h.y);
            h.z = to_tf32(ra0.z); l.z = to_tf32(ra0.z - h.z);
            h.w = to_tf32(ra0.w); l.w = to_tf32(ra0.w - h.w);
            *reinterpret_cast<float4*>(&Ah[am * GPAD + 8 * ac]) = h;
            *reinterpret_cast<float4*>(&Al[am * GPAD + 8 * ac]) = l;
            h.x = to_tf32(ra1.x); l.x = to_tf32(ra1.x - h.x);
            h.y = to_tf32(ra1.y); l.y = to_tf32(ra1.y - h.y);
            h.z = to_tf32(ra1.z); l.z = to_tf32(ra1.z - h.z);
            h.w = to_tf32(ra1.w); l.w = to_tf32(ra1.w - h.w);
            *reinterpret_cast<float4*>(&Ah[am * GPAD + 8 * ac + 4]) = h;
            *reinterpret_cast<float4*>(&Al[am * GPAD + 8 * ac + 4]) = l;
            h.x = to_tf32(rb.x); l.x = to_tf32(rb.x - h.x);
            h.y = to_tf32(rb.y); l.y = to_tf32(rb.y - h.y);
            h.z = to_tf32(rb.z); l.z = to_tf32(rb.z - h.z);
            h.w = to_tf32(rb.w); l.w = to_tf32(rb.w - h.w);
            *reinterpret_cast<float4*>(&Bh[bnr * GPAD + 4 * bq]) = h;
            *reinterpret_cast<float4*>(&Bl[bnr * GPAD + 4 * bq]) = l;
        }
        __syncthreads();
    }

    // ---- epilogue ----
    if (act != 2) {
#pragma unroll
        for (int mi = 0; mi < 2; mi++) {
            int m0 = bm + wm * 32 + mi * 16;
            int row0 = m0 + g;
            int row1 = m0 + g + 8;
#pragma unroll
            for (int ni = 0; ni < 4; ni++) {
                int col = bn + wn * 32 + ni * 8 + 2 * t;
                float b0 = bias[col], b1 = bias[col + 1];
                if (row0 < M) {
                    float v0 = acc[mi][ni][0] + b0;
                    float v1 = acc[mi][ni][1] + b1;
                    if (act == 1) { v0 = gelu_exact(v0); v1 = gelu_exact(v1); }
                    *reinterpret_cast<float2*>(&C[(size_t)row0 * N + col]) = make_float2(v0, v1);
                }
                if (row1 < M) {
                    float v2 = acc[mi][ni][2] + b0;
                    float v3 = acc[mi][ni][3] + b1;
                    if (act == 1) { v2 = gelu_exact(v2); v3 = gelu_exact(v3); }
                    *reinterpret_cast<float2*>(&C[(size_t)row1 * N + col]) = make_float2(v2, v3);
                }
            }
        }
    } else {
        // qkv-split epilogue: N=768; cols [0,256)=q (x0.125), [256,512)=k, [512,768)=v.
#pragma unroll
        for (int mi = 0; mi < 2; mi++) {
            int m0 = bm + wm * 32 + mi * 16;
#pragma unroll
            for (int ni = 0; ni < 4; ni++) {
                int col = bn + wn * 32 + ni * 8 + 2 * t;
                int sec = col >> 8;
                int d = col & 255;
                int h = d >> 6;
                int dh = d & 63;
                float* dst = (sec == 0) ? qp : (sec == 1) ? kp : vp;
                float scale = (sec == 0) ? 0.125f : 1.f;
                float b0 = bias[col], b1 = bias[col + 1];
                int row0 = m0 + g;
                int row1 = m0 + g + 8;
                if (row0 < M) {
                    int b = row0 / SEQ, s = row0 - b * SEQ;
                    size_t base = ((size_t)(b * NHEAD + h) * SEQ + s) * DHEAD + dh;
                    *reinterpret_cast<float2*>(&dst[base]) =
                        make_float2((acc[mi][ni][0] + b0) * scale, (acc[mi][ni][1] + b1) * scale);
                }
                if (row1 < M) {
                    int b = row1 / SEQ, s = row1 - b * SEQ;
                    size_t base = ((size_t)(b * NHEAD + h) * SEQ + s) * DHEAD + dh;
                    *reinterpret_cast<float2*>(&dst[base]) =
                        make_float2((acc[mi][ni][2] + b0) * scale, (acc[mi][ni][3] + b1) * scale);
                }
            }
        }
    }
}

// ---------------- gather + sum-pool ----------------
__global__ void gather_pool(const float* __restrict__ Q, const int* __restrict__ C,
                            float* __restrict__ out) {
    int o = blockIdx.x;
    int b = blockIdx.y;
    int d = threadIdx.x;
    int oz = o % 15;
    int oy = (o / 15) % 15;
    int ox = o / 225;
    const float* Qb = Q + (size_t)b * NROI * DMODEL;
    const int* Cb = C + (size_t)b * 32 * 32 * 32;
    float acc = 0.f;
#pragma unroll
    for (int dx = 0; dx < 3; dx++) {
        int x = 2 * ox + dx;
#pragma unroll
        for (int dy = 0; dy < 3; dy++) {
            int y = 2 * oy + dy;
#pragma unroll
            for (int dz = 0; dz < 3; dz++) {
                int z = 2 * oz + dz;
                int idx = Cb[(x * 32 + y) * 32 + z];
                acc += Qb[(size_t)idx * DMODEL + d];
            }
        }
    }
    out[((size_t)b * SEQ + o) * DMODEL + d] = acc;
}

// ---------------- flash attention, tf32 mma.sync ----------------
#define KPAD 68
#define VPAD 72
#define FA_SMEM ((64*68 + 64*72 + 64*68) * 4)

__global__ void __launch_bounds__(128, 3)
flash_tf32(const float* __restrict__ Qm, const float* __restrict__ Km,
           const float* __restrict__ Vm, float* __restrict__ O) {
    extern __shared__ float sm[];
    float* Ks = sm;
    float* Vs = sm + 64 * KPAD;
    float* Ps = sm + 64 * KPAD + 64 * VPAD;

    const int bh = blockIdx.y;
    const int q0 = blockIdx.x * 64;
    const int tid = threadIdx.x;
    const int warp = tid >> 5;
    const int lane = tid & 31;
    const int g = lane >> 2;
    const int t = lane & 3;

    const float* qb = Qm + (size_t)bh * SEQ * DHEAD;
    const float* kb = Km + (size_t)bh * SEQ * DHEAD;
    const float* vb = Vm + (size_t)bh * SEQ * DHEAD;

#pragma unroll
    for (int it = 0; it < 8; it++) {
        int idx = tid + it * 128;
        int row = idx >> 4;
        int c4 = (idx & 15) << 2;
        float4 v = make_float4(0.f, 0.f, 0.f, 0.f);
        if (q0 + row < SEQ) v = *reinterpret_cast<const float4*>(&qb[(size_t)(q0 + row) * 64 + c4]);
        v.x = to_tf32(v.x); v.y = to_tf32(v.y); v.z = to_tf32(v.z); v.w = to_tf32(v.w);
        *reinterpret_cast<float4*>(&Ps[row * KPAD + c4]) = v;
    }
    __syncthreads();

    const int pr = 16 * warp;
    unsigned qa[8][4];
#pragma unroll
    for (int kc = 0; kc < 8; kc++) {
        qa[kc][0] = __float_as_uint(Ps[(pr + g) * KPAD + kc * 8 + t]);
        qa[kc][1] = __float_as_uint(Ps[(pr + g + 8) * KPAD + kc * 8 + t]);
        qa[kc][2] = __float_as_uint(Ps[(pr + g) * KPAD + kc * 8 + t + 4]);
        qa[kc][3] = __float_as_uint(Ps[(pr + g + 8) * KPAD + kc * 8 + t + 4]);
    }

    float oc[8][4];
    float mi[2] = {-1e30f, -1e30f};
    float li[2] = {0.f, 0.f};
#pragma unroll
    for (int n = 0; n < 8; n++)
#pragma unroll
        for (int v = 0; v < 4; v++) oc[n][v] = 0.f;

    const int nkt = (SEQ + 63) / 64;
    for (int kt = 0; kt < nkt; kt++) {
        int k0 = kt * 64;
#pragma unroll
        for (int it = 0; it < 8; it++) {
            int idx = tid + it * 128;
            int row = idx >> 4;
            int c4 = (idx & 15) << 2;
            float4 kv = make_float4(0.f, 0.f, 0.f, 0.f);
            float4 vv = make_float4(0.f, 0.f, 0.f, 0.f);
            if (k0 + row < SEQ) {
                kv = *reinterpret_cast<const float4*>(&kb[(size_t)(k0 + row) * 64 + c4]);
                vv = *reinterpret_cast<const float4*>(&vb[(size_t)(k0 + row) * 64 + c4]);
            }
            kv.x = to_tf32(kv.x); kv.y = to_tf32(kv.y); kv.z = to_tf32(kv.z); kv.w = to_tf32(kv.w);
            vv.x = to_tf32(vv.x); vv.y = to_tf32(vv.y); vv.z = to_tf32(vv.z); vv.w = to_tf32(vv.w);
            *reinterpret_cast<float4*>(&Ks[row * KPAD + c4]) = kv;
            *reinterpret_cast<float4*>(&Vs[row * VPAD + c4]) = vv;
        }
        __syncthreads();

        float sf[8][4];
#pragma unroll
        for (int n = 0; n < 8; n++) {
            sf[n][0] = sf[n][1] = sf[n][2] = sf[n][3] = 0.f;
#pragma unroll
            for (int kc = 0; kc < 8; kc++) {
                unsigned b0 = __float_as_uint(Ks[(n * 8 + g) * KPAD + kc * 8 + t]);
                unsigned b1 = __float_as_uint(Ks[(n * 8 + g) * KPAD + kc * 8 + t + 4]);
                mma_tf32(sf[n], qa[kc], b0, b1);
            }
        }

        if (k0 + 64 > SEQ) {
            int lim = SEQ - k0;
#pragma unroll
            for (int n = 0; n < 8; n++) {
                int c0 = n * 8 + 2 * t;
                if (c0 >= lim) { sf[n][0] = -1e30f; sf[n][2] = -1e30f; }
                if (c0 + 1 >= lim) { sf[n][1] = -1e30f; sf[n][3] = -1e30f; }
            }
        }

        float tm0 = -1e30f, tm1 = -1e30f;
#pragma unroll
        for (int n = 0; n < 8; n++) {
            tm0 = fmaxf(tm0, fmaxf(sf[n][0], sf[n][1]));
            tm1 = fmaxf(tm1, fmaxf(sf[n][2], sf[n][3]));
        }
        tm0 = fmaxf(tm0, __shfl_xor_sync(0xffffffffu, tm0, 1));
        tm0 = fmaxf(tm0, __shfl_xor_sync(0xffffffffu, tm0, 2));
        tm1 = fmaxf(tm1, __shfl_xor_sync(0xffffffffu, tm1, 1));
        tm1 = fmaxf(tm1, __shfl_xor_sync(0xffffffffu, tm1, 2));
        float mn0 = fmaxf(mi[0], tm0);
        float mn1 = fmaxf(mi[1], tm1);
        float a0 = __expf(mi[0] - mn0);
        float a1 = __expf(mi[1] - mn1);
        float rs0 = 0.f, rs1 = 0.f;
#pragma unroll
        for (int n = 0; n < 8; n++) {
            float p0 = __expf(sf[n][0] - mn0);
            float p1 = __expf(sf[n][1] - mn0);
            float p2 = __expf(sf[n][2] - mn1);
            float p3 = __expf(sf[n][3] - mn1);
            rs0 += p0 + p1;
            rs1 += p2 + p3;
            float2 lo = make_float2(to_tf32(p0), to_tf32(p1));
            float2 hi = make_float2(to_tf32(p2), to_tf32(p3));
            *reinterpret_cast<float2*>(&Ps[(pr + g) * KPAD + n * 8 + 2 * t]) = lo;
            *reinterpret_cast<float2*>(&Ps[(pr + g + 8) * KPAD + n * 8 + 2 * t]) = hi;
        }
        rs0 += __shfl_xor_sync(0xffffffffu, rs0, 1);
        rs0 += __shfl_xor_sync(0xffffffffu, rs0, 2);
        rs1 += __shfl_xor_sync(0xffffffffu, rs1, 1);
        rs1 += __shfl_xor_sync(0xffffffffu, rs1, 2);
        li[0] = li[0] * a0 + rs0;
        li[1] = li[1] * a1 + rs1;
        mi[0] = mn0;
        mi[1] = mn1;
#pragma unroll
        for (int n = 0; n < 8; n++) {
            oc[n][0] *= a0; oc[n][1] *= a0;
            oc[n][2] *= a1; oc[n][3] *= a1;
        }
        __syncwarp();

#pragma unroll
        for (int kc = 0; kc < 8; kc++) {
            unsigned pa[4];
            pa[0] = __float_as_uint(Ps[(pr + g) * KPAD + kc * 8 + t]);
            pa[1] = __float_as_uint(Ps[(pr + g + 8) * KPAD + kc * 8 + t]);
            pa[2] = __float_as_uint(Ps[(pr + g) * KPAD + kc * 8 + t + 4]);
            pa[3] = __float_as_uint(Ps[(pr + g + 8) * KPAD + kc * 8 + t + 4]);
#pragma unroll
            for (int n = 0; n < 8; n++) {
                unsigned b0 = __float_as_uint(Vs[(kc * 8 + t) * VPAD + n * 8 + g]);
                unsigned b1 = __float_as_uint(Vs[(kc * 8 + t + 4) * VPAD + n * 8 + g]);
                mma_tf32(oc[n], pa, b0, b1);
            }
        }
        __syncthreads();
    }

    const int b = bh >> 2;
    const int h = bh & 3;
    float inv0 = 1.f / li[0];
    float inv1 = 1.f / li[1];
    int qr0 = q0 + pr + g;
    int qr1 = qr0 + 8;
#pragma unroll
    for (int n = 0; n < 8; n++) {
        int d = h * 64 + n * 8 + 2 * t;
        if (qr0 < SEQ) {
            float2 o2 = make_float2(oc[n][0] * inv0, oc[n][1] * inv0);
            *reinterpret_cast<float2*>(&O[((size_t)(b * SEQ + qr0)) * DMODEL + d]) = o2;
        }
        if (qr1 < SEQ) {
            float2 o2 = make_float2(oc[n][2] * inv1, oc[n][3] * inv1);
            *reinterpret_cast<float2*>(&O[((size_t)(b * SEQ + qr1)) * DMODEL + d]) = o2;
        }
    }
}

// ---------------- block stats helper ----------------
__device__ __forceinline__ void block_stats(float v, float* r1, float* r2,
                                            int d, float& mean, float& rstd) {
    __syncthreads();   // protect r1/r2 reuse across calls
    float s1 = v, s2 = v * v;
#pragma unroll
    for (int off = 16; off; off >>= 1) {
        s1 += __shfl_xor_sync(0xffffffffu, s1, off);
        s2 += __shfl_xor_sync(0xffffffffu, s2, off);
    }
    int warp = d >> 5, lane = d & 31;
    if (lane == 0) { r1[warp] = s1; r2[warp] = s2; }
    __syncthreads();
    if (d < 8) {
        float a = r1[d], b2 = r2[d];
#pragma unroll
        for (int off = 4; off; off >>= 1) {
            a += __shfl_xor_sync(0xffu, a, off);
            b2 += __shfl_xor_sync(0xffu, b2, off);
        }
        if (d == 0) { r1[0] = a; r2[0] = b2; }
    }
    __syncthreads();
    mean = r1[0] * (1.f / DMODEL);
    float var = r2[0] * (1.f / DMODEL) - mean * mean;
    rstd = rsqrtf(var + LN_EPS);
}

// ---------------- residual + LayerNorm (R may be null) ----------------
__global__ void resid_ln(const float* __restrict__ X, const float* __restrict__ R,
                         const float* __restrict__ sc, const float* __restrict__ bi,
                         float* __restrict__ out) {
    int row = blockIdx.x;
    int d = threadIdx.x;
    size_t base = (size_t)row * DMODEL;
    float v = X[base + d];
    if (R) v += R[base + d];
    __shared__ float r1[8], r2[8];
    float mean, rstd;
    block_stats(v, r1, r2, d, mean, rstd);
    out[base + d] = (v - mean) * rstd * sc[d] + bi[d];
}

// ---------------- residual + LN + LN fused (steps 9+10) ----------------
__global__ void resid_ln2(const float* __restrict__ X, const float* __restrict__ R,
                          const float* __restrict__ s1c, const float* __restrict__ b1c,
                          const float* __restrict__ s2c, const float* __restrict__ b2c,
                          float* __restrict__ out) {
    int row = blockIdx.x;
    int d = threadIdx.x;
    size_t base = (size_t)row * DMODEL;
    float v = X[base + d] + R[base + d];
    __shared__ float r1[8], r2[8];
    float mean, rstd;
    block_stats(v, r1, r2, d, mean, rstd);
    float u = (v - mean) * rstd * s1c[d] + b1c[d];
    block_stats(u, r1, r2, d, mean, rstd);
    out[base + d] = (u - mean) * rstd * s2c[d] + b2c[d];
}

// ---------------- partial mean over sequence ----------------
__global__ void mean_part(const float* __restrict__ Y, float* __restrict__ part) {
    int b = blockIdx.x;
    int c = blockIdx.y;
    int d = threadIdx.x;
    const int CH = (SEQ + 7) / 8;
    int s0 = c * CH;
    int s1 = min(SEQ, s0 + CH);
    float acc = 0.f;
    for (int s = s0; s < s1; s++)
        acc += Y[((size_t)b * SEQ + s) * DMODEL + d];
    part[(size_t)(b * 8 + c) * DMODEL + d] = acc;
}

// ---------------- classifier ----------------
__global__ void classifier(const float* __restrict__ part, const float* __restrict__ Wc,
                           const float* __restrict__ bc, float* __restrict__ out) {
    int t = threadIdx.x;
    int pair = t >> 5;
    int lane = t & 31;
    int b = pair >> 1, c = pair & 1;
    float acc = 0.f;
    for (int d = lane; d < DMODEL; d += 32) {
        float m = 0.f;
#pragma unroll
        for (int p = 0; p < 8; p++) m += part[(size_t)(b * 8 + p) * DMODEL + d];
        acc += m * Wc[c * DMODEL + d];
    }
#pragma unroll
    for (int off = 16; off; off >>= 1)
        acc += __shfl_xor_sync(0xffffffffu, acc, off);
    if (lane == 0) out[b * 2 + c] = acc * (1.f / SEQ) + bc[c];
}

// ---------------- launcher ----------------
static float* sym(const void* s) {
    void* p = nullptr;
    cudaGetSymbolAddress(&p, s);
    return (float*)p;
}

extern "C" void kernel_launch(void* const* d_in, const int* in_sizes, int n_in,
                              void* d_out, int out_size) {
    const int* C       = (const int*)d_in[0];
    const float* F     = (const float*)d_in[1];
    const float* W_fnn = (const float*)d_in[2];
    const float* b_fnn = (const float*)d_in[3];
    const float* in_w  = (const float*)d_in[4];
    const float* in_b  = (const float*)d_in[5];
    const float* out_w = (const float*)d_in[6];
    const float* out_b = (const float*)d_in[7];
    const float* ln1s  = (const float*)d_in[8];
    const float* ln1b  = (const float*)d_in[9];
    const float* W1    = (const float*)d_in[10];
    const float* b1    = (const float*)d_in[11];
    const float* W2    = (const float*)d_in[12];
    const float* b2    = (const float*)d_in[13];
    const float* ln2s  = (const float*)d_in[14];
    const float* ln2b  = (const float*)d_in[15];
    const float* ons   = (const float*)d_in[16];
    const float* onb   = (const float*)d_in[17];
    const float* Wc    = (const float*)d_in[18];
    const float* bc    = (const float*)d_in[19];
    float* out = (float*)d_out;

    float* pQ    = sym(g_Q);
    float* px    = sym(g_x);
    float* px2   = sym(g_x2);
    float* pq    = sym(g_q);
    float* pk    = sym(g_k);
    float* pv    = sym(g_v);
    float* po    = sym(g_o);
    float* pt    = sym(g_t);
    float* ph    = sym(g_h);
    float* py    = sym(g_y);
    float* ppart = sym(g_part);

    cudaFuncSetAttribute(flash_tf32, cudaFuncAttributeMaxDynamicSharedMemorySize, FA_SMEM);
    cudaFuncSetAttribute(gemm3t, cudaFuncAttributeMaxDynamicSharedMemorySize, G_SMEM);

    // 1) ROI embedding: Q = gelu(F @ W_fnn^T + b)   (6528 x 256, K=1632)
    {
        dim3 grid(DMODEL / GBN, (ROWS_Q + GBM - 1) / GBM);
        gemm3t<<<grid, 256, G_SMEM>>>(F, W_fnn, b_fnn, pQ, ROWS_Q, DMODEL, DIN, 1,
                                      nullptr, nullptr, nullptr);
    }
    // 2) gather + sum-pool -> tokens
    {
        dim3 grid(SEQ, BATCH);
        gather_pool<<<grid, DMODEL>>>(pQ, C, px);
    }
    // 3) qkv projection fused with head-split + q-scale (13500 x 768, K=256)
    {
        dim3 grid((3 * DMODEL) / GBN, (ROWS_X + GBM - 1) / GBM);
        gemm3t<<<grid, 256, G_SMEM>>>(px, in_w, in_b, nullptr, ROWS_X, 3 * DMODEL, DMODEL, 2,
                                      pq, pk, pv);
    }
    // 4) attention (tf32 tensor-core flash)
    {
        dim3 grid((SEQ + 63) / 64, BATCH * NHEAD);
        flash_tf32<<<grid, 128, FA_SMEM>>>(pq, pk, pv, po);
    }
    // 5) out projection (13500 x 256, K=256)
    {
        dim3 grid(DMODEL / GBN, (ROWS_X + GBM - 1) / GBM);
        gemm3t<<<grid, 256, G_SMEM>>>(po, out_w, out_b, pt, ROWS_X, DMODEL, DMODEL, 0,
                                      nullptr, nullptr, nullptr);
    }
    // 6) x = LN(x + o)
    resid_ln<<<ROWS_X, DMODEL>>>(px, pt, ln1s, ln1b, px2);
    // 7) FFN1: h = gelu(x @ W1^T + b1)   (13500 x 1024, K=256)
    {
        dim3 grid(DFF / GBN, (ROWS_X + GBM - 1) / GBM);
        gemm3t<<<grid, 256, G_SMEM>>>(px2, W1, b1, ph, ROWS_X, DFF, DMODEL, 1,
                                      nullptr, nullptr, nullptr);
    }
    // 8) FFN2: t = h @ W2^T + b2   (13500 x 256, K=1024)
    {
        dim3 grid(DMODEL / GBN, (ROWS_X + GBM - 1) / GBM);
        gemm3t<<<grid, 256, G_SMEM>>>(ph, W2, b2, pt, ROWS_X, DMODEL, DFF, 0,
                                      nullptr, nullptr, nullptr);
    }
    // 9+10) x = LN(x2 + t; ln2) then y = LN(x; on)  -- fused
    resid_ln2<<<ROWS_X, DMODEL>>>(px2, pt, ln2s, ln2b, ons, onb, py);
    // 11) mean over sequence
    {
        dim3 grid(BATCH, 8);
        mean_part<<<grid, DMODEL>>>(py, ppart);
    }
    // 12) classifier
    classifier<<<1, 256>>>(ppart, Wc, bc, out);
}